// round 12
// baseline (speedup 1.0000x reference)
#include <cuda_runtime.h>
#include <cuda_bf16.h>
#include <math.h>
#include <stdint.h>

#define TT 8
#define NNODE 40000
#define FF 256
#define PP 128
#define GG 128
#define HH 128
#define BB 1024
#define NE 640000
#define NNZ (NE + NNODE)
#define MALL (TT * NNODE)      // 320000 batched rows

// ------------------------- device scratch -------------------------
__device__ __align__(16) float g_h  [(size_t)MALL * PP];       // batched proj out
__device__ __align__(16) float g_m  [(size_t)MALL * GG];       // agg1(h) at S nodes (8*ns rows)
__device__ __align__(16) float g_hc [(size_t)MALL * GG];       // h1c (8*ns rows)
__device__ __align__(16) float g_mc [(size_t)TT * BB * GG];    // agg2(h1c) at targets
__device__ __align__(16) float g_h2 [(size_t)TT * BB * GG];    // h2c (8*nt rows)
__device__ __align__(16) float g_tgt[(size_t)TT * BB * (2 * GG)];
__device__ __align__(16) float g_gi [(size_t)TT * BB * (3 * HH)];
__device__ __align__(16) float g_gh [(size_t)BB * (3 * HH)];
__device__ __align__(16) float g_wihT[(size_t)(2 * GG) * (3 * HH)];
__device__ __align__(16) float g_whhT[(size_t)HH * (3 * HH)];
__device__ __align__(16) float g_gruh[(size_t)BB * HH];
__device__ __align__(16) float g_outs[(size_t)TT * BB * HH];
__device__ __align__(16) float g_val [NNZ];
__device__ __align__(16) float g_dinv[NNODE];
__device__ __align__(16) int   g_col [NNZ];
__device__ __align__(16) int   g_rowptr[NNODE + 1];
__device__ __align__(16) int   g_deg [NNODE];
__device__ __align__(16) int   g_fill[NNODE];
__device__ __align__(16) int   g_src [NE];
__device__ __align__(16) int   g_dst [NE];
__device__ __align__(16) int   g_ti  [BB];
__device__ __align__(16) int   g_tmask[NNODE];
__device__ __align__(16) int   g_smask[NNODE];
__device__ __align__(16) int   g_snodes[NNODE];
__device__ __align__(16) int   g_sidx [NNODE];
__device__ __align__(16) int   g_tidx [NNODE];
__device__ __align__(16) int   g_tnodes[BB];
__device__ int g_nt;
__device__ int g_ns;
__device__ int g_is64;

// ------------------------- packed f32x2 FMA -------------------------
__device__ __forceinline__ void ffma2(unsigned long long& d, unsigned long long a,
                                      unsigned long long b) {
    asm("fma.rn.f32x2 %0, %1, %2, %0;" : "+l"(d) : "l"(a), "l"(b));
}
__device__ __forceinline__ unsigned long long bcast2(float v) {
    unsigned long long o;
    uint32_t u = __float_as_uint(v);
    asm("mov.b64 %0, {%1, %1};" : "=l"(o) : "r"(u));
    return o;
}
__device__ __forceinline__ void unpk2(float& lo, float& hi, unsigned long long p) {
    uint32_t a, b;
    asm("mov.b64 {%0, %1}, %2;" : "=r"(a), "=r"(b) : "l"(p));
    lo = __uint_as_float(a);
    hi = __uint_as_float(b);
}

// bank-conflict-free column padding: +4 floats per 32
#define PADC(c) ((c) + (((c) >> 5) << 2))

// ------------------------- SGEMM (128x128x16 tile, 8x8/thread, FFMA2, padded smem) ---
// AS: 0 ext, 1 g_m, 2 g_mc, 3 g_tgt, 4 g_gruh ; BS: 0 ext, 1 g_wihT, 2 g_whhT
// CS: 1 g_h, 2 g_hc, 3 g_h2, 4 g_gi, 5 g_gh ; MSEL: 0 param, 1 8*g_ns, 2 8*g_nt
template<int AS, int BS, int CS, int MSEL, bool RELU, bool BIAS>
__global__ void __launch_bounds__(256) sgemm2(const float* __restrict__ Aext,
                                              const float* __restrict__ Bext,
                                              const float* __restrict__ bias,
                                              int Mparam, int N, int K)
{
    int M;
    if constexpr (MSEL == 1)      M = 8 * g_ns;
    else if constexpr (MSEL == 2) M = 8 * g_nt;
    else                          M = Mparam;
    int rowBase = blockIdx.y * 128;
    if (rowBase >= M) return;

    const float* A;
    if constexpr (AS == 1)      A = g_m;
    else if constexpr (AS == 2) A = g_mc;
    else if constexpr (AS == 3) A = g_tgt;
    else if constexpr (AS == 4) A = g_gruh;
    else                        A = Aext;
    const float* B;
    if constexpr (BS == 1)      B = g_wihT;
    else if constexpr (BS == 2) B = g_whhT;
    else                        B = Bext;
    float* C;
    if constexpr (CS == 1)      C = g_h;
    else if constexpr (CS == 2) C = g_hc;
    else if constexpr (CS == 3) C = g_h2;
    else if constexpr (CS == 4) C = g_gi;
    else                        C = g_gh;

    const int BK = 16;
    __shared__ __align__(16) float As[BK][132];   // stride 132: STS 4-way -> 2-way
    __shared__ __align__(16) float Bs[BK][144];   // PADC layout: LDS.128 conflict-free
    int tid = threadIdx.x;
    int tx = tid % 16, ty = tid / 16;
    int colBase = blockIdx.x * 128;

    // acc2[i][j]: row ty*8+i, cols (tx*8+2j, tx*8+2j+1)
    unsigned long long acc2[8][4];
#pragma unroll
    for (int i = 0; i < 8; i++)
#pragma unroll
        for (int j = 0; j < 4; j++) acc2[i][j] = 0ULL;

    int aRow = tid >> 2;
    int aCol = (tid & 3) * 4;
    int bRow = tid >> 5;
    int bCol = (tid & 31) * 4;
    int bColP = PADC(bCol);
    int rdA = ty * 8;                      // broadcast read base (row group)
    int rdB0 = PADC(tx * 8);
    int rdB1 = PADC(tx * 8 + 4);

    for (int k0 = 0; k0 < K; k0 += BK) {
#pragma unroll
        for (int p = 0; p < 2; p++) {
            int r = aRow + p * 64;
            int gr = rowBase + r;
            float4 v = make_float4(0.f, 0.f, 0.f, 0.f);
            if (gr < M) v = *(const float4*)(A + (size_t)gr * K + k0 + aCol);
            As[aCol + 0][r] = v.x; As[aCol + 1][r] = v.y;
            As[aCol + 2][r] = v.z; As[aCol + 3][r] = v.w;
        }
#pragma unroll
        for (int p = 0; p < 2; p++) {
            int r = bRow + p * 8;
            float4 v = *(const float4*)(B + (size_t)(k0 + r) * N + colBase + bCol);
            *(float4*)&Bs[r][bColP] = v;
        }
        __syncthreads();
#pragma unroll
        for (int kk = 0; kk < BK; kk++) {
            float4 a0 = *(const float4*)&As[kk][rdA];
            float4 a1 = *(const float4*)&As[kk][rdA + 4];
            unsigned long long av[8];
            av[0] = bcast2(a0.x); av[1] = bcast2(a0.y);
            av[2] = bcast2(a0.z); av[3] = bcast2(a0.w);
            av[4] = bcast2(a1.x); av[5] = bcast2(a1.y);
            av[6] = bcast2(a1.z); av[7] = bcast2(a1.w);
            ulonglong2 b0 = *(const ulonglong2*)&Bs[kk][rdB0];
            ulonglong2 b1 = *(const ulonglong2*)&Bs[kk][rdB1];
            unsigned long long bv[4] = {b0.x, b0.y, b1.x, b1.y};
#pragma unroll
            for (int i = 0; i < 8; i++)
#pragma unroll
                for (int j = 0; j < 4; j++) ffma2(acc2[i][j], av[i], bv[j]);
        }
        __syncthreads();
    }

    // epilogue
#pragma unroll
    for (int i = 0; i < 8; i++) {
        int gr = rowBase + ty * 8 + i;
        if (gr >= M) continue;
        float c[8];
#pragma unroll
        for (int j = 0; j < 4; j++) unpk2(c[2 * j], c[2 * j + 1], acc2[i][j]);
#pragma unroll
        for (int j = 0; j < 8; j += 4) {
            int gc = colBase + tx * 8 + j;
            float4 o;
            o.x = c[j]; o.y = c[j + 1]; o.z = c[j + 2]; o.w = c[j + 3];
            if (BIAS) {
                o.x += bias[gc]; o.y += bias[gc + 1];
                o.z += bias[gc + 2]; o.w += bias[gc + 3];
            }
            if (RELU) {
                o.x = fmaxf(o.x, 0.f); o.y = fmaxf(o.y, 0.f);
                o.z = fmaxf(o.z, 0.f); o.w = fmaxf(o.w, 0.f);
            }
            *(float4*)(C + (size_t)gr * N + gc) = o;
        }
    }
}

// ------------------------- index dtype detection + conversion -------------------------
__global__ void k_detect(const unsigned int* __restrict__ wdata, int n_elems) {
    __shared__ int bad;
    if (threadIdx.x == 0) bad = 0;
    __syncthreads();
    int limit = n_elems < 4096 ? n_elems : 4096;
    for (int i = threadIdx.x; i < limit; i += blockDim.x)
        if (wdata[2 * i + 1] != 0u) bad = 1;
    __syncthreads();
    if (threadIdx.x == 0) g_is64 = bad ? 0 : 1;
}

__device__ __forceinline__ int clampN(int v) {
    return v < 0 ? 0 : (v >= NNODE ? NNODE - 1 : v);
}

__global__ void k_cvt_edges(const void* __restrict__ ei) {
    int e = blockIdx.x * blockDim.x + threadIdx.x;
    if (e < NE) {
        int s, d;
        if (g_is64) {
            const long long* p = (const long long*)ei;
            s = (int)p[e]; d = (int)p[NE + e];
        } else {
            const int* p = (const int*)ei;
            s = p[e]; d = p[NE + e];
        }
        g_src[e] = clampN(s);
        g_dst[e] = clampN(d);
    }
}

__global__ void k_cvt_ti(const void* __restrict__ ti) {
    int b = blockIdx.x * blockDim.x + threadIdx.x;
    if (b < BB) {
        int v;
        if (g_is64) v = (int)((const long long*)ti)[b];
        else        v = ((const int*)ti)[b];
        g_ti[b] = clampN(v);
    }
}

// ------------------------- graph preprocessing -------------------------
__global__ void k_init_deg() {
    int i = blockIdx.x * blockDim.x + threadIdx.x;
    if (i < NNODE) { g_deg[i] = 1; g_fill[i] = 0; }
    if (i == 0) { g_nt = 0; g_ns = 0; }
}

__global__ void k_deg_edges() {
    int e = blockIdx.x * blockDim.x + threadIdx.x;
    if (e < NE) atomicAdd(&g_deg[g_dst[e]], 1);
}

__global__ void k_dinv() {
    int i = blockIdx.x * blockDim.x + threadIdx.x;
    if (i < NNODE) g_dinv[i] = rsqrtf((float)g_deg[i]);
}

__global__ void k_scan() {
    const int CH = 40;
    int t = threadIdx.x;
    int lane = t & 31, wid = t >> 5;
    int beg = t * CH;
    int sum = 0;
    for (int i = 0; i < CH; i++) {
        int idx = beg + i;
        if (idx < NNODE) sum += g_deg[idx];
    }
    int v = sum;
    for (int o = 1; o < 32; o <<= 1) {
        int u = __shfl_up_sync(0xffffffffu, v, o);
        if (lane >= o) v += u;
    }
    __shared__ int wsum[32];
    if (lane == 31) wsum[wid] = v;
    __syncthreads();
    if (wid == 0) {
        int w2 = wsum[lane];
        for (int o = 1; o < 32; o <<= 1) {
            int u = __shfl_up_sync(0xffffffffu, w2, o);
            if (lane >= o) w2 += u;
        }
        wsum[lane] = w2;
    }
    __syncthreads();
    int run = v - sum + (wid > 0 ? wsum[wid - 1] : 0);
    for (int i = 0; i < CH; i++) {
        int idx = beg + i;
        if (idx < NNODE) {
            g_rowptr[idx] = run;
            run += g_deg[idx];
        }
    }
    if (t == 1023) g_rowptr[NNODE] = run;
}

__global__ void k_selfloop() {
    int n = blockIdx.x * blockDim.x + threadIdx.x;
    if (n < NNODE) {
        int pos = g_rowptr[n];
        g_col[pos] = n;
        float d = g_dinv[n];
        g_val[pos] = d * d;
        g_fill[n] = 1;
    }
}

__global__ void k_fill_edges() {
    int e = blockIdx.x * blockDim.x + threadIdx.x;
    if (e < NE) {
        int s = g_src[e];
        int d = g_dst[e];
        int pos = g_rowptr[d] + atomicAdd(&g_fill[d], 1);
        g_col[pos] = s;
        g_val[pos] = g_dinv[s] * g_dinv[d];
    }
}

// ------------------------- target-neighborhood compaction -------------------------
__global__ void k_clear_masks() {
    int i = blockIdx.x * blockDim.x + threadIdx.x;
    if (i < NNODE) { g_tmask[i] = 0; g_smask[i] = 0; }
}
__global__ void k_mark_t() {
    int b = blockIdx.x * blockDim.x + threadIdx.x;
    if (b < BB) g_tmask[g_ti[b]] = 1;
}
__global__ void k_mark_s() {
    int e = blockIdx.x * blockDim.x + threadIdx.x;
    if (e < NE && g_tmask[g_dst[e]]) g_smask[g_src[e]] = 1;
}
__global__ void k_mark_s2() {
    int n = blockIdx.x * blockDim.x + threadIdx.x;
    if (n < NNODE && g_tmask[n]) g_smask[n] = 1;
}
__global__ void k_compact() {
    int n = blockIdx.x * blockDim.x + threadIdx.x;
    if (n < NNODE) {
        if (g_tmask[n]) {
            int ix = atomicAdd(&g_nt, 1);
            g_tnodes[ix] = n;
            g_tidx[n] = ix;
        }
        if (g_smask[n]) {
            int ix = atomicAdd(&g_ns, 1);
            g_snodes[ix] = n;
            g_sidx[n] = ix;
        }
    }
}

// ------------------------- batched aggregations (pre-GEMM, linearity) ----------------
__global__ void k_agg1_all()
{
    int warp = (blockIdx.x * blockDim.x + threadIdx.x) >> 5;
    int lane = threadIdx.x & 31;
    int ns = g_ns;
    if (warp >= TT * ns) return;
    int t = warp / ns;
    int i = warp - t * ns;
    int node = g_snodes[i];
    int s0 = g_rowptr[node], s1 = g_rowptr[node + 1];
    const float4* h4 = (const float4*)g_h;
    size_t hbase = (size_t)t * NNODE * 32;
    float4 acc = make_float4(0.f, 0.f, 0.f, 0.f);
    for (int e = s0; e < s1; e++) {
        float v = g_val[e];
        float4 x = h4[hbase + (size_t)g_col[e] * 32 + lane];
        acc.x = fmaf(v, x.x, acc.x); acc.y = fmaf(v, x.y, acc.y);
        acc.z = fmaf(v, x.z, acc.z); acc.w = fmaf(v, x.w, acc.w);
    }
    ((float4*)g_m)[(size_t)warp * 32 + lane] = acc;
}

__global__ void k_agg2_all()
{
    int warp = (blockIdx.x * blockDim.x + threadIdx.x) >> 5;
    int lane = threadIdx.x & 31;
    int nt = g_nt;
    if (warp >= TT * nt) return;
    int t = warp / nt;
    int i = warp - t * nt;
    int node = g_tnodes[i];
    int s0 = g_rowptr[node], s1 = g_rowptr[node + 1];
    const float4* h4 = (const float4*)g_hc;
    size_t hbase = (size_t)t * g_ns * 32;
    float4 acc = make_float4(0.f, 0.f, 0.f, 0.f);
    for (int e = s0; e < s1; e++) {
        float v = g_val[e];
        float4 x = h4[hbase + (size_t)g_sidx[g_col[e]] * 32 + lane];
        acc.x = fmaf(v, x.x, acc.x); acc.y = fmaf(v, x.y, acc.y);
        acc.z = fmaf(v, x.z, acc.z); acc.w = fmaf(v, x.w, acc.w);
    }
    ((float4*)g_mc)[(size_t)warp * 32 + lane] = acc;
}

// ------------------------- gather targets (all t) -------------------------
__global__ void k_gather_all() {
    int b = blockIdx.x;
    int t = blockIdx.y;
    int f = threadIdx.x;                   // 256
    int node = g_ti[b];
    float v = (f < GG) ? g_hc[((size_t)t * g_ns + g_sidx[node]) * GG + f]
                       : g_h2[((size_t)t * g_nt + g_tidx[node]) * GG + (f - GG)];
    g_tgt[((size_t)t * BB + b) * (2 * GG) + f] = v;
}

// ------------------------- weight transposes / zero -------------------------
__global__ void k_transpose_wih(const float* __restrict__ w) {
    int i = blockIdx.x * blockDim.x + threadIdx.x;
    if (i < 384 * 256) {
        int jj = i / 256, k = i % 256;
        g_wihT[(size_t)k * 384 + jj] = w[i];
    }
}
__global__ void k_transpose_whh(const float* __restrict__ w) {
    int i = blockIdx.x * blockDim.x + threadIdx.x;
    if (i < 384 * 128) {
        int jj = i / 128, k = i % 128;
        g_whhT[(size_t)k * 384 + jj] = w[i];
    }
}
__global__ void k_zero_h0() {
    int i = blockIdx.x * blockDim.x + threadIdx.x;
    if (i < BB * HH) g_gruh[i] = 0.f;
}

// ------------------------- GRU pointwise -------------------------
__device__ __forceinline__ float sigmoidf_(float x) { return 1.f / (1.f + expf(-x)); }

__global__ void k_gru_pt(int t) {
    int idx = blockIdx.x * blockDim.x + threadIdx.x;
    if (idx >= BB * HH) return;
    int b = idx >> 7, j = idx & 127;
    size_t gir = ((size_t)t * BB + b) * 384;
    size_t ghr = (size_t)b * 384;
    float hr = g_gh[ghr + j], hz = g_gh[ghr + 128 + j], hg = g_gh[ghr + 256 + j];
    float h = g_gruh[idx];
    float r = sigmoidf_(g_gi[gir + j] + hr);
    float z = sigmoidf_(g_gi[gir + 128 + j] + hz);
    float g = tanhf(g_gi[gir + 256 + j] + r * hg);
    float hn = (1.f - z) * g + z * h;
    g_gruh[idx] = hn;
    g_outs[(size_t)t * BB * HH + idx] = hn;
}

// ------------------------- attention + prediction head -------------------------
__global__ void k_final(const float* __restrict__ attn_w, const float* __restrict__ attn_b,
                        const float* __restrict__ pw1, const float* __restrict__ pb1,
                        const float* __restrict__ pw2, const float* __restrict__ pb2,
                        float* __restrict__ out)
{
    int b = blockIdx.x;
    int j = threadIdx.x;                   // 128
    __shared__ float so[TT][HH];
    __shared__ float red[HH];
    __shared__ float sc[TT];
    __shared__ float w8[TT];
    __shared__ float hm[16];

#pragma unroll
    for (int t = 0; t < TT; t++) so[t][j] = g_outs[((size_t)t * BB + b) * HH + j];
    float aw = attn_w[j];
    __syncthreads();

    for (int t = 0; t < TT; t++) {
        red[j] = so[t][j] * aw;
        __syncthreads();
        for (int off = 64; off > 0; off >>= 1) {
            if (j < off) red[j] += red[j + off];
            __syncthreads();
        }
        if (j == 0) sc[t] = tanhf(red[0] + attn_b[0]);
        __syncthreads();
    }
    if (j == 0) {
        float mx = sc[0];
        for (int t = 1; t < TT; t++) mx = fmaxf(mx, sc[t]);
        float s = 0.f;
        for (int t = 0; t < TT; t++) { w8[t] = expf(sc[t] - mx); s += w8[t]; }
        float inv = 1.f / s;
        for (int t = 0; t < TT; t++) w8[t] *= inv;
    }
    __syncthreads();
    float rep = 0.f;
#pragma unroll
    for (int t = 0; t < TT; t++) rep = fmaf(w8[t], so[t][j], rep);
    red[j] = rep;
    __syncthreads();
    if (j < 16) {
        float s = pb1[j];
        for (int k = 0; k < HH; k++) s = fmaf(red[k], pw1[k * 16 + j], s);
        hm[j] = fmaxf(s, 0.f);
    }
    __syncthreads();
    if (j == 0) {
        float p = pb2[0];
#pragma unroll
        for (int k = 0; k < 16; k++) p = fmaf(hm[k], pw2[k], p);
        out[b] = p;
    }
    if (j < TT) out[BB + b * TT + j] = w8[j];
}

// ------------------------- launch -------------------------
extern "C" void kernel_launch(void* const* d_in, const int* in_sizes, int n_in,
                              void* d_out, int out_size)
{
    const float* x       = (const float*)d_in[0];
    const void*  ei      = d_in[1];
    const void*  ti      = d_in[2];
    const float* proj_w  = (const float*)d_in[3];
    const float* proj_b  = (const float*)d_in[4];
    const float* gcn_w1  = (const float*)d_in[5];
    const float* gcn_b1  = (const float*)d_in[6];
    const float* gcn_w2  = (const float*)d_in[7];
    const float* gcn_b2  = (const float*)d_in[8];
    const float* gru_w_ih = (const float*)d_in[9];
    const float* gru_w_hh = (const float*)d_in[10];
    const float* gru_b_ih = (const float*)d_in[11];
    const float* gru_b_hh = (const float*)d_in[12];
    const float* attn_w  = (const float*)d_in[13];
    const float* attn_b  = (const float*)d_in[14];
    const float* pred_w1 = (const float*)d_in[15];
    const float* pred_b1 = (const float*)d_in[16];
    const float* pred_w2 = (const float*)d_in[17];
    const float* pred_b2 = (const float*)d_in[18];
    float* out = (float*)d_out;

    dim3 gAll(1, (MALL + 127) / 128);
    dim3 gG2(1, (TT * BB + 127) / 128);
    dim3 gGi(3, (TT * BB + 127) / 128);
    dim3 gGru(3, (BB + 127) / 128);
    const int agg1Blocks = (MALL * 32 + 255) / 256;
    const int agg2Blocks = (TT * BB * 32 + 255) / 256;
    dim3 gGather(BB, TT);

    // index 3 = batched proj GEMM (ncu captures launch 3)
    k_detect<<<1, 1024>>>((const unsigned int*)ei, BB);                          // 0
    k_cvt_ti<<<(BB + 255) / 256, 256>>>(ti);                                     // 1
    k_cvt_edges<<<(NE + 255) / 256, 256>>>(ei);                                  // 2
    sgemm2<0, 0, 1, 0, true, true><<<gAll, 256>>>(x, proj_w, proj_b, MALL, PP, FF); // 3
    k_transpose_wih<<<(384 * 256 + 255) / 256, 256>>>(gru_w_ih);                 // 4
    k_transpose_whh<<<(384 * 128 + 255) / 256, 256>>>(gru_w_hh);                 // 5

    // graph preprocessing
    k_init_deg<<<(NNODE + 255) / 256, 256>>>();
    k_deg_edges<<<(NE + 255) / 256, 256>>>();
    k_dinv<<<(NNODE + 255) / 256, 256>>>();
    k_scan<<<1, 1024>>>();
    k_selfloop<<<(NNODE + 255) / 256, 256>>>();
    k_fill_edges<<<(NE + 255) / 256, 256>>>();
    k_clear_masks<<<(NNODE + 255) / 256, 256>>>();
    k_mark_t<<<(BB + 255) / 256, 256>>>();
    k_mark_s<<<(NE + 255) / 256, 256>>>();
    k_mark_s2<<<(NNODE + 255) / 256, 256>>>();
    k_compact<<<(NNODE + 255) / 256, 256>>>();
    k_zero_h0<<<(BB * HH + 255) / 256, 256>>>();

    // GCN via linearity: agg first, GEMM on compact rows
    k_agg1_all<<<agg1Blocks, 256>>>();
    sgemm2<1, 0, 2, 1, true, true><<<gAll, 256>>>(nullptr, gcn_w1, gcn_b1, 0, GG, PP);
    k_agg2_all<<<agg2Blocks, 256>>>();
    sgemm2<2, 0, 3, 2, true, true><<<gG2, 256>>>(nullptr, gcn_w2, gcn_b2, 0, GG, GG);
    k_gather_all<<<gGather, 256>>>();

    // GI = tgt (8192 x 256) @ wihT + b_ih
    sgemm2<3, 1, 4, 0, false, true><<<gGi, 256>>>(nullptr, nullptr, gru_b_ih, TT * BB, 3 * HH, 2 * GG);

    for (int t = 0; t < TT; t++) {
        sgemm2<4, 2, 5, 0, false, true><<<gGru, 256>>>(nullptr, nullptr, gru_b_hh, BB, 3 * HH, HH);
        k_gru_pt<<<(BB * HH + 255) / 256, 256>>>(t);
    }

    k_final<<<BB, HH>>>(attn_w, attn_b, pred_w1, pred_b1, pred_w2, pred_b2, out);
}

// round 13
// speedup vs baseline: 1.3907x; 1.3907x over previous
#include <cuda_runtime.h>
#include <cuda_bf16.h>
#include <math.h>
#include <stdint.h>

#define TT 8
#define NNODE 40000
#define FF 256
#define PP 128
#define GG 128
#define HH 128
#define BB 1024
#define NE 640000
#define NNZ (NE + NNODE)
#define MALL (TT * NNODE)      // 320000 batched rows

// ------------------------- device scratch -------------------------
__device__ __align__(16) float g_h  [(size_t)MALL * PP];
__device__ __align__(16) float g_m  [(size_t)MALL * GG];
__device__ __align__(16) float g_hc [(size_t)MALL * GG];
__device__ __align__(16) float g_mc [(size_t)TT * BB * GG];
__device__ __align__(16) float g_h2 [(size_t)TT * BB * GG];
__device__ __align__(16) float g_tgt[(size_t)TT * BB * (2 * GG)];
__device__ __align__(16) float g_gi [(size_t)TT * BB * (3 * HH)];
__device__ __align__(16) float g_gh [(size_t)BB * (3 * HH)];
__device__ __align__(16) float g_wihT[(size_t)(2 * GG) * (3 * HH)];
__device__ __align__(16) float g_whhT[(size_t)HH * (3 * HH)];
__device__ __align__(16) float g_gruh[(size_t)BB * HH];
__device__ __align__(16) float g_outs[(size_t)TT * BB * HH];
__device__ __align__(16) float g_val [NNZ];
__device__ __align__(16) float g_dinv[NNODE];
__device__ __align__(16) int   g_col [NNZ];
__device__ __align__(16) int   g_rowptr[NNODE + 1];
__device__ __align__(16) int   g_deg [NNODE];
__device__ __align__(16) int   g_fill[NNODE];
__device__ __align__(16) int   g_src [NE];
__device__ __align__(16) int   g_dst [NE];
__device__ __align__(16) int   g_ti  [BB];
__device__ __align__(16) int   g_tmask[NNODE];
__device__ __align__(16) int   g_smask[NNODE];
__device__ __align__(16) int   g_snodes[NNODE];
__device__ __align__(16) int   g_sidx [NNODE];
__device__ __align__(16) int   g_tidx [NNODE];
__device__ __align__(16) int   g_tnodes[BB];
__device__ int g_nt;
__device__ int g_ns;
__device__ int g_is64;

// ------------------------- packed f32x2 FMA -------------------------
__device__ __forceinline__ void ffma2(unsigned long long& d, unsigned long long a,
                                      unsigned long long b) {
    asm("fma.rn.f32x2 %0, %1, %2, %0;" : "+l"(d) : "l"(a), "l"(b));
}
__device__ __forceinline__ unsigned long long bcast2(float v) {
    unsigned long long o;
    uint32_t u = __float_as_uint(v);
    asm("mov.b64 %0, {%1, %1};" : "=l"(o) : "r"(u));
    return o;
}
__device__ __forceinline__ void unpk2(float& lo, float& hi, unsigned long long p) {
    uint32_t a, b;
    asm("mov.b64 {%0, %1}, %2;" : "=r"(a), "=r"(b) : "l"(p));
    lo = __uint_as_float(a);
    hi = __uint_as_float(b);
}

// ------------------------- SGEMM (128x128x16, 8x8/thread, FFMA2, double-buffered) ----
// AS: 0 ext, 1 g_m, 2 g_mc, 3 g_tgt, 4 g_gruh ; BS: 0 ext, 1 g_wihT, 2 g_whhT
// CS: 1 g_h, 2 g_hc, 3 g_h2, 4 g_gi, 5 g_gh ; MSEL: 0 param, 1 8*g_ns, 2 8*g_nt
template<int AS, int BS, int CS, int MSEL, bool RELU, bool BIAS>
__global__ void __launch_bounds__(256) sgemm2(const float* __restrict__ Aext,
                                              const float* __restrict__ Bext,
                                              const float* __restrict__ bias,
                                              int Mparam, int N, int K)
{
    int M;
    if constexpr (MSEL == 1)      M = 8 * g_ns;
    else if constexpr (MSEL == 2) M = 8 * g_nt;
    else                          M = Mparam;
    int rowBase = blockIdx.y * 128;
    if (rowBase >= M) return;

    const float* A;
    if constexpr (AS == 1)      A = g_m;
    else if constexpr (AS == 2) A = g_mc;
    else if constexpr (AS == 3) A = g_tgt;
    else if constexpr (AS == 4) A = g_gruh;
    else                        A = Aext;
    const float* B;
    if constexpr (BS == 1)      B = g_wihT;
    else if constexpr (BS == 2) B = g_whhT;
    else                        B = Bext;
    float* C;
    if constexpr (CS == 1)      C = g_h;
    else if constexpr (CS == 2) C = g_hc;
    else if constexpr (CS == 3) C = g_h2;
    else if constexpr (CS == 4) C = g_gi;
    else                        C = g_gh;

    const int BK = 16;
    __shared__ __align__(16) float As[2][BK][128];
    __shared__ __align__(16) float Bs[2][BK][128];
    int tid = threadIdx.x;
    int tx = tid % 16, ty = tid / 16;
    int colBase = blockIdx.x * 128;

    unsigned long long acc2[8][4];
#pragma unroll
    for (int i = 0; i < 8; i++)
#pragma unroll
        for (int j = 0; j < 4; j++) acc2[i][j] = 0ULL;

    int aRow = tid >> 2;
    int aCol = (tid & 3) * 4;
    int bRow = tid >> 5;
    int bCol = (tid & 31) * 4;

    // registers for staged tile
    float4 va0, va1, vb0, vb1;

    // ---- prologue: load tile k0=0 and store to buffer 0 ----
    {
        int gr0 = rowBase + aRow;
        int gr1 = rowBase + aRow + 64;
        va0 = make_float4(0.f, 0.f, 0.f, 0.f);
        va1 = make_float4(0.f, 0.f, 0.f, 0.f);
        if (gr0 < M) va0 = *(const float4*)(A + (size_t)gr0 * K + aCol);
        if (gr1 < M) va1 = *(const float4*)(A + (size_t)gr1 * K + aCol);
        vb0 = *(const float4*)(B + (size_t)bRow * N + colBase + bCol);
        vb1 = *(const float4*)(B + (size_t)(bRow + 8) * N + colBase + bCol);
        As[0][aCol + 0][aRow] = va0.x; As[0][aCol + 1][aRow] = va0.y;
        As[0][aCol + 2][aRow] = va0.z; As[0][aCol + 3][aRow] = va0.w;
        As[0][aCol + 0][aRow + 64] = va1.x; As[0][aCol + 1][aRow + 64] = va1.y;
        As[0][aCol + 2][aRow + 64] = va1.z; As[0][aCol + 3][aRow + 64] = va1.w;
        *(float4*)&Bs[0][bRow][bCol] = vb0;
        *(float4*)&Bs[0][bRow + 8][bCol] = vb1;
    }
    __syncthreads();

    int buf = 0;
    for (int k0 = 0; k0 < K; k0 += BK) {
        bool hasNext = (k0 + BK < K);
        // ---- prefetch next tile into registers (LDG overlaps compute) ----
        if (hasNext) {
            int kn = k0 + BK;
            int gr0 = rowBase + aRow;
            int gr1 = rowBase + aRow + 64;
            va0 = make_float4(0.f, 0.f, 0.f, 0.f);
            va1 = make_float4(0.f, 0.f, 0.f, 0.f);
            if (gr0 < M) va0 = *(const float4*)(A + (size_t)gr0 * K + kn + aCol);
            if (gr1 < M) va1 = *(const float4*)(A + (size_t)gr1 * K + kn + aCol);
            vb0 = *(const float4*)(B + (size_t)(kn + bRow) * N + colBase + bCol);
            vb1 = *(const float4*)(B + (size_t)(kn + bRow + 8) * N + colBase + bCol);
        }
        // ---- compute on current buffer ----
#pragma unroll
        for (int kk = 0; kk < BK; kk++) {
            float4 a0 = *(const float4*)&As[buf][kk][ty * 8];
            float4 a1 = *(const float4*)&As[buf][kk][ty * 8 + 4];
            unsigned long long av[8];
            av[0] = bcast2(a0.x); av[1] = bcast2(a0.y);
            av[2] = bcast2(a0.z); av[3] = bcast2(a0.w);
            av[4] = bcast2(a1.x); av[5] = bcast2(a1.y);
            av[6] = bcast2(a1.z); av[7] = bcast2(a1.w);
            ulonglong2 b0 = *(const ulonglong2*)&Bs[buf][kk][tx * 8];
            ulonglong2 b1 = *(const ulonglong2*)&Bs[buf][kk][tx * 8 + 4];
            unsigned long long bv[4] = {b0.x, b0.y, b1.x, b1.y};
#pragma unroll
            for (int i = 0; i < 8; i++)
#pragma unroll
                for (int j = 0; j < 4; j++) ffma2(acc2[i][j], av[i], bv[j]);
        }
        // ---- store prefetched tile to other buffer ----
        if (hasNext) {
            int nb = buf ^ 1;
            As[nb][aCol + 0][aRow] = va0.x; As[nb][aCol + 1][aRow] = va0.y;
            As[nb][aCol + 2][aRow] = va0.z; As[nb][aCol + 3][aRow] = va0.w;
            As[nb][aCol + 0][aRow + 64] = va1.x; As[nb][aCol + 1][aRow + 64] = va1.y;
            As[nb][aCol + 2][aRow + 64] = va1.z; As[nb][aCol + 3][aRow + 64] = va1.w;
            *(float4*)&Bs[nb][bRow][bCol] = vb0;
            *(float4*)&Bs[nb][bRow + 8][bCol] = vb1;
            __syncthreads();
        }
        buf ^= 1;
    }

    // epilogue
#pragma unroll
    for (int i = 0; i < 8; i++) {
        int gr = rowBase + ty * 8 + i;
        if (gr >= M) continue;
        float c[8];
#pragma unroll
        for (int j = 0; j < 4; j++) unpk2(c[2 * j], c[2 * j + 1], acc2[i][j]);
#pragma unroll
        for (int j = 0; j < 8; j += 4) {
            int gc = colBase + tx * 8 + j;
            float4 o;
            o.x = c[j]; o.y = c[j + 1]; o.z = c[j + 2]; o.w = c[j + 3];
            if (BIAS) {
                o.x += bias[gc]; o.y += bias[gc + 1];
                o.z += bias[gc + 2]; o.w += bias[gc + 3];
            }
            if (RELU) {
                o.x = fmaxf(o.x, 0.f); o.y = fmaxf(o.y, 0.f);
                o.z = fmaxf(o.z, 0.f); o.w = fmaxf(o.w, 0.f);
            }
            *(float4*)(C + (size_t)gr * N + gc) = o;
        }
    }
}

// ------------------------- index dtype detection + conversion -------------------------
__global__ void k_detect(const unsigned int* __restrict__ wdata, int n_elems) {
    __shared__ int bad;
    if (threadIdx.x == 0) bad = 0;
    __syncthreads();
    int limit = n_elems < 4096 ? n_elems : 4096;
    for (int i = threadIdx.x; i < limit; i += blockDim.x)
        if (wdata[2 * i + 1] != 0u) bad = 1;
    __syncthreads();
    if (threadIdx.x == 0) g_is64 = bad ? 0 : 1;
}

__device__ __forceinline__ int clampN(int v) {
    return v < 0 ? 0 : (v >= NNODE ? NNODE - 1 : v);
}

__global__ void k_cvt_edges(const void* __restrict__ ei) {
    int e = blockIdx.x * blockDim.x + threadIdx.x;
    if (e < NE) {
        int s, d;
        if (g_is64) {
            const long long* p = (const long long*)ei;
            s = (int)p[e]; d = (int)p[NE + e];
        } else {
            const int* p = (const int*)ei;
            s = p[e]; d = p[NE + e];
        }
        g_src[e] = clampN(s);
        g_dst[e] = clampN(d);
    }
}

__global__ void k_cvt_ti(const void* __restrict__ ti) {
    int b = blockIdx.x * blockDim.x + threadIdx.x;
    if (b < BB) {
        int v;
        if (g_is64) v = (int)((const long long*)ti)[b];
        else        v = ((const int*)ti)[b];
        g_ti[b] = clampN(v);
    }
}

// ------------------------- graph preprocessing -------------------------
__global__ void k_init_deg() {
    int i = blockIdx.x * blockDim.x + threadIdx.x;
    if (i < NNODE) { g_deg[i] = 1; g_fill[i] = 0; }
    if (i == 0) { g_nt = 0; g_ns = 0; }
}

__global__ void k_deg_edges() {
    int e = blockIdx.x * blockDim.x + threadIdx.x;
    if (e < NE) atomicAdd(&g_deg[g_dst[e]], 1);
}

__global__ void k_dinv() {
    int i = blockIdx.x * blockDim.x + threadIdx.x;
    if (i < NNODE) g_dinv[i] = rsqrtf((float)g_deg[i]);
}

__global__ void k_scan() {
    const int CH = 40;
    int t = threadIdx.x;
    int lane = t & 31, wid = t >> 5;
    int beg = t * CH;
    int sum = 0;
    for (int i = 0; i < CH; i++) {
        int idx = beg + i;
        if (idx < NNODE) sum += g_deg[idx];
    }
    int v = sum;
    for (int o = 1; o < 32; o <<= 1) {
        int u = __shfl_up_sync(0xffffffffu, v, o);
        if (lane >= o) v += u;
    }
    __shared__ int wsum[32];
    if (lane == 31) wsum[wid] = v;
    __syncthreads();
    if (wid == 0) {
        int w2 = wsum[lane];
        for (int o = 1; o < 32; o <<= 1) {
            int u = __shfl_up_sync(0xffffffffu, w2, o);
            if (lane >= o) w2 += u;
        }
        wsum[lane] = w2;
    }
    __syncthreads();
    int run = v - sum + (wid > 0 ? wsum[wid - 1] : 0);
    for (int i = 0; i < CH; i++) {
        int idx = beg + i;
        if (idx < NNODE) {
            g_rowptr[idx] = run;
            run += g_deg[idx];
        }
    }
    if (t == 1023) g_rowptr[NNODE] = run;
}

__global__ void k_selfloop() {
    int n = blockIdx.x * blockDim.x + threadIdx.x;
    if (n < NNODE) {
        int pos = g_rowptr[n];
        g_col[pos] = n;
        float d = g_dinv[n];
        g_val[pos] = d * d;
        g_fill[n] = 1;
    }
}

__global__ void k_fill_edges() {
    int e = blockIdx.x * blockDim.x + threadIdx.x;
    if (e < NE) {
        int s = g_src[e];
        int d = g_dst[e];
        int pos = g_rowptr[d] + atomicAdd(&g_fill[d], 1);
        g_col[pos] = s;
        g_val[pos] = g_dinv[s] * g_dinv[d];
    }
}

// ------------------------- target-neighborhood compaction -------------------------
__global__ void k_clear_masks() {
    int i = blockIdx.x * blockDim.x + threadIdx.x;
    if (i < NNODE) { g_tmask[i] = 0; g_smask[i] = 0; }
}
__global__ void k_mark_t() {
    int b = blockIdx.x * blockDim.x + threadIdx.x;
    if (b < BB) g_tmask[g_ti[b]] = 1;
}
__global__ void k_mark_s() {
    int e = blockIdx.x * blockDim.x + threadIdx.x;
    if (e < NE && g_tmask[g_dst[e]]) g_smask[g_src[e]] = 1;
}
__global__ void k_mark_s2() {
    int n = blockIdx.x * blockDim.x + threadIdx.x;
    if (n < NNODE && g_tmask[n]) g_smask[n] = 1;
}
__global__ void k_compact() {
    int n = blockIdx.x * blockDim.x + threadIdx.x;
    if (n < NNODE) {
        if (g_tmask[n]) {
            int ix = atomicAdd(&g_nt, 1);
            g_tnodes[ix] = n;
            g_tidx[n] = ix;
        }
        if (g_smask[n]) {
            int ix = atomicAdd(&g_ns, 1);
            g_snodes[ix] = n;
            g_sidx[n] = ix;
        }
    }
}

// ------------------------- batched aggregations (pre-GEMM, linearity) ----------------
__global__ void k_agg1_all()
{
    int warp = (blockIdx.x * blockDim.x + threadIdx.x) >> 5;
    int lane = threadIdx.x & 31;
    int ns = g_ns;
    if (warp >= TT * ns) return;
    int t = warp / ns;
    int i = warp - t * ns;
    int node = g_snodes[i];
    int s0 = g_rowptr[node], s1 = g_rowptr[node + 1];
    const float4* h4 = (const float4*)g_h;
    size_t hbase = (size_t)t * NNODE * 32;
    float4 acc = make_float4(0.f, 0.f, 0.f, 0.f);
    for (int e = s0; e < s1; e++) {
        float v = g_val[e];
        float4 x = h4[hbase + (size_t)g_col[e] * 32 + lane];
        acc.x = fmaf(v, x.x, acc.x); acc.y = fmaf(v, x.y, acc.y);
        acc.z = fmaf(v, x.z, acc.z); acc.w = fmaf(v, x.w, acc.w);
    }
    ((float4*)g_m)[(size_t)warp * 32 + lane] = acc;
}

__global__ void k_agg2_all()
{
    int warp = (blockIdx.x * blockDim.x + threadIdx.x) >> 5;
    int lane = threadIdx.x & 31;
    int nt = g_nt;
    if (warp >= TT * nt) return;
    int t = warp / nt;
    int i = warp - t * nt;
    int node = g_tnodes[i];
    int s0 = g_rowptr[node], s1 = g_rowptr[node + 1];
    const float4* h4 = (const float4*)g_hc;
    size_t hbase = (size_t)t * g_ns * 32;
    float4 acc = make_float4(0.f, 0.f, 0.f, 0.f);
    for (int e = s0; e < s1; e++) {
        float v = g_val[e];
        float4 x = h4[hbase + (size_t)g_sidx[g_col[e]] * 32 + lane];
        acc.x = fmaf(v, x.x, acc.x); acc.y = fmaf(v, x.y, acc.y);
        acc.z = fmaf(v, x.z, acc.z); acc.w = fmaf(v, x.w, acc.w);
    }
    ((float4*)g_mc)[(size_t)warp * 32 + lane] = acc;
}

// ------------------------- gather targets (all t) -------------------------
__global__ void k_gather_all() {
    int b = blockIdx.x;
    int t = blockIdx.y;
    int f = threadIdx.x;                   // 256
    int node = g_ti[b];
    float v = (f < GG) ? g_hc[((size_t)t * g_ns + g_sidx[node]) * GG + f]
                       : g_h2[((size_t)t * g_nt + g_tidx[node]) * GG + (f - GG)];
    g_tgt[((size_t)t * BB + b) * (2 * GG) + f] = v;
}

// ------------------------- weight transposes / zero -------------------------
__global__ void k_transpose_wih(const float* __restrict__ w) {
    int i = blockIdx.x * blockDim.x + threadIdx.x;
    if (i < 384 * 256) {
        int jj = i / 256, k = i % 256;
        g_wihT[(size_t)k * 384 + jj] = w[i];
    }
}
__global__ void k_transpose_whh(const float* __restrict__ w) {
    int i = blockIdx.x * blockDim.x + threadIdx.x;
    if (i < 384 * 128) {
        int jj = i / 128, k = i % 128;
        g_whhT[(size_t)k * 384 + jj] = w[i];
    }
}
__global__ void k_zero_h0() {
    int i = blockIdx.x * blockDim.x + threadIdx.x;
    if (i < BB * HH) g_gruh[i] = 0.f;
}

// ------------------------- GRU pointwise -------------------------
__device__ __forceinline__ float sigmoidf_(float x) { return 1.f / (1.f + expf(-x)); }

__global__ void k_gru_pt(int t) {
    int idx = blockIdx.x * blockDim.x + threadIdx.x;
    if (idx >= BB * HH) return;
    int b = idx >> 7, j = idx & 127;
    size_t gir = ((size_t)t * BB + b) * 384;
    size_t ghr = (size_t)b * 384;
    float hr = g_gh[ghr + j], hz = g_gh[ghr + 128 + j], hg = g_gh[ghr + 256 + j];
    float h = g_gruh[idx];
    float r = sigmoidf_(g_gi[gir + j] + hr);
    float z = sigmoidf_(g_gi[gir + 128 + j] + hz);
    float g = tanhf(g_gi[gir + 256 + j] + r * hg);
    float hn = (1.f - z) * g + z * h;
    g_gruh[idx] = hn;
    g_outs[(size_t)t * BB * HH + idx] = hn;
}

// ------------------------- attention + prediction head -------------------------
__global__ void k_final(const float* __restrict__ attn_w, const float* __restrict__ attn_b,
                        const float* __restrict__ pw1, const float* __restrict__ pb1,
                        const float* __restrict__ pw2, const float* __restrict__ pb2,
                        float* __restrict__ out)
{
    int b = blockIdx.x;
    int j = threadIdx.x;                   // 128
    __shared__ float so[TT][HH];
    __shared__ float red[HH];
    __shared__ float sc[TT];
    __shared__ float w8[TT];
    __shared__ float hm[16];

#pragma unroll
    for (int t = 0; t < TT; t++) so[t][j] = g_outs[((size_t)t * BB + b) * HH + j];
    float aw = attn_w[j];
    __syncthreads();

    for (int t = 0; t < TT; t++) {
        red[j] = so[t][j] * aw;
        __syncthreads();
        for (int off = 64; off > 0; off >>= 1) {
            if (j < off) red[j] += red[j + off];
            __syncthreads();
        }
        if (j == 0) sc[t] = tanhf(red[0] + attn_b[0]);
        __syncthreads();
    }
    if (j == 0) {
        float mx = sc[0];
        for (int t = 1; t < TT; t++) mx = fmaxf(mx, sc[t]);
        float s = 0.f;
        for (int t = 0; t < TT; t++) { w8[t] = expf(sc[t] - mx); s += w8[t]; }
        float inv = 1.f / s;
        for (int t = 0; t < TT; t++) w8[t] *= inv;
    }
    __syncthreads();
    float rep = 0.f;
#pragma unroll
    for (int t = 0; t < TT; t++) rep = fmaf(w8[t], so[t][j], rep);
    red[j] = rep;
    __syncthreads();
    if (j < 16) {
        float s = pb1[j];
        for (int k = 0; k < HH; k++) s = fmaf(red[k], pw1[k * 16 + j], s);
        hm[j] = fmaxf(s, 0.f);
    }
    __syncthreads();
    if (j == 0) {
        float p = pb2[0];
#pragma unroll
        for (int k = 0; k < 16; k++) p = fmaf(hm[k], pw2[k], p);
        out[b] = p;
    }
    if (j < TT) out[BB + b * TT + j] = w8[j];
}

// ------------------------- launch -------------------------
extern "C" void kernel_launch(void* const* d_in, const int* in_sizes, int n_in,
                              void* d_out, int out_size)
{
    const float* x       = (const float*)d_in[0];
    const void*  ei      = d_in[1];
    const void*  ti      = d_in[2];
    const float* proj_w  = (const float*)d_in[3];
    const float* proj_b  = (const float*)d_in[4];
    const float* gcn_w1  = (const float*)d_in[5];
    const float* gcn_b1  = (const float*)d_in[6];
    const float* gcn_w2  = (const float*)d_in[7];
    const float* gcn_b2  = (const float*)d_in[8];
    const float* gru_w_ih = (const float*)d_in[9];
    const float* gru_w_hh = (const float*)d_in[10];
    const float* gru_b_ih = (const float*)d_in[11];
    const float* gru_b_hh = (const float*)d_in[12];
    const float* attn_w  = (const float*)d_in[13];
    const float* attn_b  = (const float*)d_in[14];
    const float* pred_w1 = (const float*)d_in[15];
    const float* pred_b1 = (const float*)d_in[16];
    const float* pred_w2 = (const float*)d_in[17];
    const float* pred_b2 = (const float*)d_in[18];
    float* out = (float*)d_out;

    dim3 gAll(1, (MALL + 127) / 128);
    dim3 gG2(1, (TT * BB + 127) / 128);
    dim3 gGi(3, (TT * BB + 127) / 128);
    dim3 gGru(3, (BB + 127) / 128);
    const int agg1Blocks = (MALL * 32 + 255) / 256;
    const int agg2Blocks = (TT * BB * 32 + 255) / 256;
    dim3 gGather(BB, TT);

    // index 3 = batched proj GEMM (ncu captures launch 3)
    k_detect<<<1, 1024>>>((const unsigned int*)ei, BB);                          // 0
    k_cvt_ti<<<(BB + 255) / 256, 256>>>(ti);                                     // 1
    k_cvt_edges<<<(NE + 255) / 256, 256>>>(ei);                                  // 2
    sgemm2<0, 0, 1, 0, true, true><<<gAll, 256>>>(x, proj_w, proj_b, MALL, PP, FF); // 3
    k_transpose_wih<<<(384 * 256 + 255) / 256, 256>>>(gru_w_ih);                 // 4
    k_transpose_whh<<<(384 * 128 + 255) / 256, 256>>>(gru_w_hh);                 // 5

    // graph preprocessing
    k_init_deg<<<(NNODE + 255) / 256, 256>>>();
    k_deg_edges<<<(NE + 255) / 256, 256>>>();
    k_dinv<<<(NNODE + 255) / 256, 256>>>();
    k_scan<<<1, 1024>>>();
    k_selfloop<<<(NNODE + 255) / 256, 256>>>();
    k_fill_edges<<<(NE + 255) / 256, 256>>>();
    k_clear_masks<<<(NNODE + 255) / 256, 256>>>();
    k_mark_t<<<(BB + 255) / 256, 256>>>();
    k_mark_s<<<(NE + 255) / 256, 256>>>();
    k_mark_s2<<<(NNODE + 255) / 256, 256>>>();
    k_compact<<<(NNODE + 255) / 256, 256>>>();
    k_zero_h0<<<(BB * HH + 255) / 256, 256>>>();

    // GCN via linearity: agg first, GEMM on compact rows
    k_agg1_all<<<agg1Blocks, 256>>>();
    sgemm2<1, 0, 2, 1, true, true><<<gAll, 256>>>(nullptr, gcn_w1, gcn_b1, 0, GG, PP);
    k_agg2_all<<<agg2Blocks, 256>>>();
    sgemm2<2, 0, 3, 2, true, true><<<gG2, 256>>>(nullptr, gcn_w2, gcn_b2, 0, GG, GG);
    k_gather_all<<<gGather, 256>>>();

    // GI = tgt (8192 x 256) @ wihT + b_ih
    sgemm2<3, 1, 4, 0, false, true><<<gGi, 256>>>(nullptr, nullptr, gru_b_ih, TT * BB, 3 * HH, 2 * GG);

    for (int t = 0; t < TT; t++) {
        sgemm2<4, 2, 5, 0, false, true><<<gGru, 256>>>(nullptr, nullptr, gru_b_hh, BB, 3 * HH, HH);
        k_gru_pt<<<(BB * HH + 255) / 256, 256>>>(t);
    }

    k_final<<<BB, HH>>>(attn_w, attn_b, pred_w1, pred_b1, pred_w2, pred_b2, out);
}

// round 14
// speedup vs baseline: 1.4479x; 1.0411x over previous
#include <cuda_runtime.h>
#include <cuda_bf16.h>
#include <math.h>
#include <stdint.h>

#define TT 8
#define NNODE 40000
#define FF 256
#define PP 128
#define GG 128
#define HH 128
#define BB 1024
#define NE 640000
#define NNZ (NE + NNODE)
#define MALL (TT * NNODE)      // 320000 batched rows

// ------------------------- device scratch -------------------------
__device__ __align__(16) float g_h  [(size_t)MALL * PP];
__device__ __align__(16) float g_m  [(size_t)MALL * GG];
__device__ __align__(16) float g_hc [(size_t)MALL * GG];
__device__ __align__(16) float g_mc [(size_t)TT * BB * GG];
__device__ __align__(16) float g_h2 [(size_t)TT * BB * GG];
__device__ __align__(16) float g_tgt[(size_t)TT * BB * (2 * GG)];
__device__ __align__(16) float g_gi [(size_t)TT * BB * (3 * HH)];
__device__ __align__(16) float g_gh [(size_t)BB * (3 * HH)];
__device__ __align__(16) float g_wihT[(size_t)(2 * GG) * (3 * HH)];
__device__ __align__(16) float g_whhT[(size_t)HH * (3 * HH)];
__device__ __align__(16) float g_gruh[(size_t)BB * HH];
__device__ __align__(16) float g_outs[(size_t)TT * BB * HH];
__device__ __align__(16) float g_val [NNZ];
__device__ __align__(16) float g_dinv[NNODE];
__device__ __align__(16) int   g_col [NNZ];
__device__ __align__(16) int   g_rowptr[NNODE + 1];
__device__ __align__(16) int   g_deg [NNODE];
__device__ __align__(16) int   g_fill[NNODE];
__device__ __align__(16) int   g_src [NE];
__device__ __align__(16) int   g_dst [NE];
__device__ __align__(16) int   g_ti  [BB];
__device__ __align__(16) int   g_tmask[NNODE];
__device__ __align__(16) int   g_smask[NNODE];
__device__ __align__(16) int   g_snodes[NNODE];
__device__ __align__(16) int   g_sidx [NNODE];
__device__ __align__(16) int   g_tidx [NNODE];
__device__ __align__(16) int   g_tnodes[BB];
__device__ int g_nt;
__device__ int g_ns;
__device__ int g_is64;

// ------------------------- packed f32x2 FMA -------------------------
__device__ __forceinline__ void ffma2(unsigned long long& d, unsigned long long a,
                                      unsigned long long b) {
    asm("fma.rn.f32x2 %0, %1, %2, %0;" : "+l"(d) : "l"(a), "l"(b));
}
__device__ __forceinline__ unsigned long long bcast2(float v) {
    unsigned long long o;
    uint32_t u = __float_as_uint(v);
    asm("mov.b64 %0, {%1, %1};" : "=l"(o) : "r"(u));
    return o;
}
__device__ __forceinline__ void unpk2(float& lo, float& hi, unsigned long long p) {
    uint32_t a, b;
    asm("mov.b64 {%0, %1}, %2;" : "=r"(a), "=r"(b) : "l"(p));
    lo = __uint_as_float(a);
    hi = __uint_as_float(b);
}

// ------------------------- SGEMM (128x128x16, 8x8/thread, FFMA2, conflict-free) ------
// B cols per thread: {tx*4..+3} U {64+tx*4..+3} -> conflict-free LDS/STS, pow2 strides.
// A staged row-per-thread -> conflict-free STS; reads broadcast.
// AS: 0 ext, 1 g_m, 2 g_mc, 3 g_tgt, 4 g_gruh ; BS: 0 ext, 1 g_wihT, 2 g_whhT
// CS: 1 g_h, 2 g_hc, 3 g_h2, 4 g_gi, 5 g_gh ; MSEL: 0 param, 1 8*g_ns, 2 8*g_nt
template<int AS, int BS, int CS, int MSEL, bool RELU, bool BIAS>
__global__ void __launch_bounds__(256) sgemm2(const float* __restrict__ Aext,
                                              const float* __restrict__ Bext,
                                              const float* __restrict__ bias,
                                              int Mparam, int N, int K)
{
    int M;
    if constexpr (MSEL == 1)      M = 8 * g_ns;
    else if constexpr (MSEL == 2) M = 8 * g_nt;
    else                          M = Mparam;
    int rowBase = blockIdx.y * 128;
    if (rowBase >= M) return;

    const float* A;
    if constexpr (AS == 1)      A = g_m;
    else if constexpr (AS == 2) A = g_mc;
    else if constexpr (AS == 3) A = g_tgt;
    else if constexpr (AS == 4) A = g_gruh;
    else                        A = Aext;
    const float* B;
    if constexpr (BS == 1)      B = g_wihT;
    else if constexpr (BS == 2) B = g_whhT;
    else                        B = Bext;
    float* C;
    if constexpr (CS == 1)      C = g_h;
    else if constexpr (CS == 2) C = g_hc;
    else if constexpr (CS == 3) C = g_h2;
    else if constexpr (CS == 4) C = g_gi;
    else                        C = g_gh;

    const int BK = 16;
    __shared__ __align__(16) float As[2][BK][128];
    __shared__ __align__(16) float Bs[2][BK][128];
    int tid = threadIdx.x;
    int tx = tid % 16, ty = tid / 16;
    int colBase = blockIdx.x * 128;

    // acc2[i][j]: row ty*8+i ; j<2 -> cols tx*4+2j.. ; j>=2 -> cols 64+tx*4+2(j-2)..
    unsigned long long acc2[8][4];
#pragma unroll
    for (int i = 0; i < 8; i++)
#pragma unroll
        for (int j = 0; j < 4; j++) acc2[i][j] = 0ULL;

    // A loader: thread -> (row = tid&127, k-half = (tid>>7)*8)
    int aRow = tid & 127;
    int aK   = (tid >> 7) * 8;
    // B loader: thread -> (row = tid>>4, cols bC..bC+3 and 64+bC..64+bC+3)
    int bRow = tid >> 4;
    int bC   = (tid & 15) * 4;

    int gr = rowBase + aRow;
    bool rowOK = (gr < M);
    const float* Arow = A + (size_t)(rowOK ? gr : 0) * K + aK;

    float4 va0, va1, vb0, vb1;

    // ---- prologue: tile 0 -> buffer 0 ----
    va0 = make_float4(0.f, 0.f, 0.f, 0.f);
    va1 = make_float4(0.f, 0.f, 0.f, 0.f);
    if (rowOK) {
        va0 = *(const float4*)(Arow);
        va1 = *(const float4*)(Arow + 4);
    }
    vb0 = *(const float4*)(B + (size_t)bRow * N + colBase + bC);
    vb1 = *(const float4*)(B + (size_t)bRow * N + colBase + 64 + bC);
    As[0][aK + 0][aRow] = va0.x; As[0][aK + 1][aRow] = va0.y;
    As[0][aK + 2][aRow] = va0.z; As[0][aK + 3][aRow] = va0.w;
    As[0][aK + 4][aRow] = va1.x; As[0][aK + 5][aRow] = va1.y;
    As[0][aK + 6][aRow] = va1.z; As[0][aK + 7][aRow] = va1.w;
    *(float4*)&Bs[0][bRow][bC] = vb0;
    *(float4*)&Bs[0][bRow][64 + bC] = vb1;
    __syncthreads();

    int buf = 0;
    for (int k0 = 0; k0 < K; k0 += BK) {
        bool hasNext = (k0 + BK < K);
        if (hasNext) {
            int kn = k0 + BK;
            va0 = make_float4(0.f, 0.f, 0.f, 0.f);
            va1 = make_float4(0.f, 0.f, 0.f, 0.f);
            if (rowOK) {
                va0 = *(const float4*)(Arow + kn);
                va1 = *(const float4*)(Arow + kn + 4);
            }
            vb0 = *(const float4*)(B + (size_t)(kn + bRow) * N + colBase + bC);
            vb1 = *(const float4*)(B + (size_t)(kn + bRow) * N + colBase + 64 + bC);
        }
#pragma unroll
        for (int kk = 0; kk < BK; kk++) {
            float4 a0 = *(const float4*)&As[buf][kk][ty * 8];
            float4 a1 = *(const float4*)&As[buf][kk][ty * 8 + 4];
            unsigned long long av[8];
            av[0] = bcast2(a0.x); av[1] = bcast2(a0.y);
            av[2] = bcast2(a0.z); av[3] = bcast2(a0.w);
            av[4] = bcast2(a1.x); av[5] = bcast2(a1.y);
            av[6] = bcast2(a1.z); av[7] = bcast2(a1.w);
            ulonglong2 b0 = *(const ulonglong2*)&Bs[buf][kk][tx * 4];
            ulonglong2 b1 = *(const ulonglong2*)&Bs[buf][kk][64 + tx * 4];
            unsigned long long bv[4] = {b0.x, b0.y, b1.x, b1.y};
#pragma unroll
            for (int i = 0; i < 8; i++)
#pragma unroll
                for (int j = 0; j < 4; j++) ffma2(acc2[i][j], av[i], bv[j]);
        }
        if (hasNext) {
            int nb = buf ^ 1;
            As[nb][aK + 0][aRow] = va0.x; As[nb][aK + 1][aRow] = va0.y;
            As[nb][aK + 2][aRow] = va0.z; As[nb][aK + 3][aRow] = va0.w;
            As[nb][aK + 4][aRow] = va1.x; As[nb][aK + 5][aRow] = va1.y;
            As[nb][aK + 6][aRow] = va1.z; As[nb][aK + 7][aRow] = va1.w;
            *(float4*)&Bs[nb][bRow][bC] = vb0;
            *(float4*)&Bs[nb][bRow][64 + bC] = vb1;
            __syncthreads();
        }
        buf ^= 1;
    }

    // epilogue: two float4 stores per row (cols tx*4.. and 64+tx*4..)
#pragma unroll
    for (int i = 0; i < 8; i++) {
        int grr = rowBase + ty * 8 + i;
        if (grr >= M) continue;
        float c[8];
#pragma unroll
        for (int j = 0; j < 4; j++) unpk2(c[2 * j], c[2 * j + 1], acc2[i][j]);
        int gc0 = colBase + tx * 4;
        int gc1 = colBase + 64 + tx * 4;
        float4 o0, o1;
        o0.x = c[0]; o0.y = c[1]; o0.z = c[2]; o0.w = c[3];
        o1.x = c[4]; o1.y = c[5]; o1.z = c[6]; o1.w = c[7];
        if (BIAS) {
            o0.x += bias[gc0]; o0.y += bias[gc0 + 1];
            o0.z += bias[gc0 + 2]; o0.w += bias[gc0 + 3];
            o1.x += bias[gc1]; o1.y += bias[gc1 + 1];
            o1.z += bias[gc1 + 2]; o1.w += bias[gc1 + 3];
        }
        if (RELU) {
            o0.x = fmaxf(o0.x, 0.f); o0.y = fmaxf(o0.y, 0.f);
            o0.z = fmaxf(o0.z, 0.f); o0.w = fmaxf(o0.w, 0.f);
            o1.x = fmaxf(o1.x, 0.f); o1.y = fmaxf(o1.y, 0.f);
            o1.z = fmaxf(o1.z, 0.f); o1.w = fmaxf(o1.w, 0.f);
        }
        *(float4*)(C + (size_t)grr * N + gc0) = o0;
        *(float4*)(C + (size_t)grr * N + gc1) = o1;
    }
}

// ------------------------- index dtype detection + conversion -------------------------
__global__ void k_detect(const unsigned int* __restrict__ wdata, int n_elems) {
    __shared__ int bad;
    if (threadIdx.x == 0) bad = 0;
    __syncthreads();
    int limit = n_elems < 4096 ? n_elems : 4096;
    for (int i = threadIdx.x; i < limit; i += blockDim.x)
        if (wdata[2 * i + 1] != 0u) bad = 1;
    __syncthreads();
    if (threadIdx.x == 0) g_is64 = bad ? 0 : 1;
}

__device__ __forceinline__ int clampN(int v) {
    return v < 0 ? 0 : (v >= NNODE ? NNODE - 1 : v);
}

__global__ void k_cvt_edges(const void* __restrict__ ei) {
    int e = blockIdx.x * blockDim.x + threadIdx.x;
    if (e < NE) {
        int s, d;
        if (g_is64) {
            const long long* p = (const long long*)ei;
            s = (int)p[e]; d = (int)p[NE + e];
        } else {
            const int* p = (const int*)ei;
            s = p[e]; d = p[NE + e];
        }
        g_src[e] = clampN(s);
        g_dst[e] = clampN(d);
    }
}

__global__ void k_cvt_ti(const void* __restrict__ ti) {
    int b = blockIdx.x * blockDim.x + threadIdx.x;
    if (b < BB) {
        int v;
        if (g_is64) v = (int)((const long long*)ti)[b];
        else        v = ((const int*)ti)[b];
        g_ti[b] = clampN(v);
    }
}

// ------------------------- graph preprocessing -------------------------
__global__ void k_init_deg() {
    int i = blockIdx.x * blockDim.x + threadIdx.x;
    if (i < NNODE) { g_deg[i] = 1; g_fill[i] = 0; }
    if (i == 0) { g_nt = 0; g_ns = 0; }
}

__global__ void k_deg_edges() {
    int e = blockIdx.x * blockDim.x + threadIdx.x;
    if (e < NE) atomicAdd(&g_deg[g_dst[e]], 1);
}

__global__ void k_dinv() {
    int i = blockIdx.x * blockDim.x + threadIdx.x;
    if (i < NNODE) g_dinv[i] = rsqrtf((float)g_deg[i]);
}

__global__ void k_scan() {
    const int CH = 40;
    int t = threadIdx.x;
    int lane = t & 31, wid = t >> 5;
    int beg = t * CH;
    int sum = 0;
    for (int i = 0; i < CH; i++) {
        int idx = beg + i;
        if (idx < NNODE) sum += g_deg[idx];
    }
    int v = sum;
    for (int o = 1; o < 32; o <<= 1) {
        int u = __shfl_up_sync(0xffffffffu, v, o);
        if (lane >= o) v += u;
    }
    __shared__ int wsum[32];
    if (lane == 31) wsum[wid] = v;
    __syncthreads();
    if (wid == 0) {
        int w2 = wsum[lane];
        for (int o = 1; o < 32; o <<= 1) {
            int u = __shfl_up_sync(0xffffffffu, w2, o);
            if (lane >= o) w2 += u;
        }
        wsum[lane] = w2;
    }
    __syncthreads();
    int run = v - sum + (wid > 0 ? wsum[wid - 1] : 0);
    for (int i = 0; i < CH; i++) {
        int idx = beg + i;
        if (idx < NNODE) {
            g_rowptr[idx] = run;
            run += g_deg[idx];
        }
    }
    if (t == 1023) g_rowptr[NNODE] = run;
}

__global__ void k_selfloop() {
    int n = blockIdx.x * blockDim.x + threadIdx.x;
    if (n < NNODE) {
        int pos = g_rowptr[n];
        g_col[pos] = n;
        float d = g_dinv[n];
        g_val[pos] = d * d;
        g_fill[n] = 1;
    }
}

__global__ void k_fill_edges() {
    int e = blockIdx.x * blockDim.x + threadIdx.x;
    if (e < NE) {
        int s = g_src[e];
        int d = g_dst[e];
        int pos = g_rowptr[d] + atomicAdd(&g_fill[d], 1);
        g_col[pos] = s;
        g_val[pos] = g_dinv[s] * g_dinv[d];
    }
}

// ------------------------- target-neighborhood compaction -------------------------
__global__ void k_clear_masks() {
    int i = blockIdx.x * blockDim.x + threadIdx.x;
    if (i < NNODE) { g_tmask[i] = 0; g_smask[i] = 0; }
}
__global__ void k_mark_t() {
    int b = blockIdx.x * blockDim.x + threadIdx.x;
    if (b < BB) g_tmask[g_ti[b]] = 1;
}
__global__ void k_mark_s() {
    int e = blockIdx.x * blockDim.x + threadIdx.x;
    if (e < NE && g_tmask[g_dst[e]]) g_smask[g_src[e]] = 1;
}
__global__ void k_mark_s2() {
    int n = blockIdx.x * blockDim.x + threadIdx.x;
    if (n < NNODE && g_tmask[n]) g_smask[n] = 1;
}
__global__ void k_compact() {
    int n = blockIdx.x * blockDim.x + threadIdx.x;
    if (n < NNODE) {
        if (g_tmask[n]) {
            int ix = atomicAdd(&g_nt, 1);
            g_tnodes[ix] = n;
            g_tidx[n] = ix;
        }
        if (g_smask[n]) {
            int ix = atomicAdd(&g_ns, 1);
            g_snodes[ix] = n;
            g_sidx[n] = ix;
        }
    }
}

// ------------------------- batched aggregations (pre-GEMM, linearity) ----------------
__global__ void k_agg1_all()
{
    int warp = (blockIdx.x * blockDim.x + threadIdx.x) >> 5;
    int lane = threadIdx.x & 31;
    int ns = g_ns;
    if (warp >= TT * ns) return;
    int t = warp / ns;
    int i = warp - t * ns;
    int node = g_snodes[i];
    int s0 = g_rowptr[node], s1 = g_rowptr[node + 1];
    const float4* h4 = (const float4*)g_h;
    size_t hbase = (size_t)t * NNODE * 32;
    float4 acc = make_float4(0.f, 0.f, 0.f, 0.f);
    for (int e = s0; e < s1; e++) {
        float v = g_val[e];
        float4 x = h4[hbase + (size_t)g_col[e] * 32 + lane];
        acc.x = fmaf(v, x.x, acc.x); acc.y = fmaf(v, x.y, acc.y);
        acc.z = fmaf(v, x.z, acc.z); acc.w = fmaf(v, x.w, acc.w);
    }
    ((float4*)g_m)[(size_t)warp * 32 + lane] = acc;
}

__global__ void k_agg2_all()
{
    int warp = (blockIdx.x * blockDim.x + threadIdx.x) >> 5;
    int lane = threadIdx.x & 31;
    int nt = g_nt;
    if (warp >= TT * nt) return;
    int t = warp / nt;
    int i = warp - t * nt;
    int node = g_tnodes[i];
    int s0 = g_rowptr[node], s1 = g_rowptr[node + 1];
    const float4* h4 = (const float4*)g_hc;
    size_t hbase = (size_t)t * g_ns * 32;
    float4 acc = make_float4(0.f, 0.f, 0.f, 0.f);
    for (int e = s0; e < s1; e++) {
        float v = g_val[e];
        float4 x = h4[hbase + (size_t)g_sidx[g_col[e]] * 32 + lane];
        acc.x = fmaf(v, x.x, acc.x); acc.y = fmaf(v, x.y, acc.y);
        acc.z = fmaf(v, x.z, acc.z); acc.w = fmaf(v, x.w, acc.w);
    }
    ((float4*)g_mc)[(size_t)warp * 32 + lane] = acc;
}

// ------------------------- gather targets (all t) -------------------------
__global__ void k_gather_all() {
    int b = blockIdx.x;
    int t = blockIdx.y;
    int f = threadIdx.x;                   // 256
    int node = g_ti[b];
    float v = (f < GG) ? g_hc[((size_t)t * g_ns + g_sidx[node]) * GG + f]
                       : g_h2[((size_t)t * g_nt + g_tidx[node]) * GG + (f - GG)];
    g_tgt[((size_t)t * BB + b) * (2 * GG) + f] = v;
}

// ------------------------- weight transposes / zero -------------------------
__global__ void k_transpose_wih(const float* __restrict__ w) {
    int i = blockIdx.x * blockDim.x + threadIdx.x;
    if (i < 384 * 256) {
        int jj = i / 256, k = i % 256;
        g_wihT[(size_t)k * 384 + jj] = w[i];
    }
}
__global__ void k_transpose_whh(const float* __restrict__ w) {
    int i = blockIdx.x * blockDim.x + threadIdx.x;
    if (i < 384 * 128) {
        int jj = i / 128, k = i % 128;
        g_whhT[(size_t)k * 384 + jj] = w[i];
    }
}
__global__ void k_zero_h0() {
    int i = blockIdx.x * blockDim.x + threadIdx.x;
    if (i < BB * HH) g_gruh[i] = 0.f;
}

// ------------------------- GRU pointwise -------------------------
__device__ __forceinline__ float sigmoidf_(float x) { return 1.f / (1.f + expf(-x)); }

__global__ void k_gru_pt(int t) {
    int idx = blockIdx.x * blockDim.x + threadIdx.x;
    if (idx >= BB * HH) return;
    int b = idx >> 7, j = idx & 127;
    size_t gir = ((size_t)t * BB + b) * 384;
    size_t ghr = (size_t)b * 384;
    float hr = g_gh[ghr + j], hz = g_gh[ghr + 128 + j], hg = g_gh[ghr + 256 + j];
    float h = g_gruh[idx];
    float r = sigmoidf_(g_gi[gir + j] + hr);
    float z = sigmoidf_(g_gi[gir + 128 + j] + hz);
    float g = tanhf(g_gi[gir + 256 + j] + r * hg);
    float hn = (1.f - z) * g + z * h;
    g_gruh[idx] = hn;
    g_outs[(size_t)t * BB * HH + idx] = hn;
}

// ------------------------- attention + prediction head -------------------------
__global__ void k_final(const float* __restrict__ attn_w, const float* __restrict__ attn_b,
                        const float* __restrict__ pw1, const float* __restrict__ pb1,
                        const float* __restrict__ pw2, const float* __restrict__ pb2,
                        float* __restrict__ out)
{
    int b = blockIdx.x;
    int j = threadIdx.x;                   // 128
    __shared__ float so[TT][HH];
    __shared__ float red[HH];
    __shared__ float sc[TT];
    __shared__ float w8[TT];
    __shared__ float hm[16];

#pragma unroll
    for (int t = 0; t < TT; t++) so[t][j] = g_outs[((size_t)t * BB + b) * HH + j];
    float aw = attn_w[j];
    __syncthreads();

    for (int t = 0; t < TT; t++) {
        red[j] = so[t][j] * aw;
        __syncthreads();
        for (int off = 64; off > 0; off >>= 1) {
            if (j < off) red[j] += red[j + off];
            __syncthreads();
        }
        if (j == 0) sc[t] = tanhf(red[0] + attn_b[0]);
        __syncthreads();
    }
    if (j == 0) {
        float mx = sc[0];
        for (int t = 1; t < TT; t++) mx = fmaxf(mx, sc[t]);
        float s = 0.f;
        for (int t = 0; t < TT; t++) { w8[t] = expf(sc[t] - mx); s += w8[t]; }
        float inv = 1.f / s;
        for (int t = 0; t < TT; t++) w8[t] *= inv;
    }
    __syncthreads();
    float rep = 0.f;
#pragma unroll
    for (int t = 0; t < TT; t++) rep = fmaf(w8[t], so[t][j], rep);
    red[j] = rep;
    __syncthreads();
    if (j < 16) {
        float s = pb1[j];
        for (int k = 0; k < HH; k++) s = fmaf(red[k], pw1[k * 16 + j], s);
        hm[j] = fmaxf(s, 0.f);
    }
    __syncthreads();
    if (j == 0) {
        float p = pb2[0];
#pragma unroll
        for (int k = 0; k < 16; k++) p = fmaf(hm[k], pw2[k], p);
        out[b] = p;
    }
    if (j < TT) out[BB + b * TT + j] = w8[j];
}

// ------------------------- launch -------------------------
extern "C" void kernel_launch(void* const* d_in, const int* in_sizes, int n_in,
                              void* d_out, int out_size)
{
    const float* x       = (const float*)d_in[0];
    const void*  ei      = d_in[1];
    const void*  ti      = d_in[2];
    const float* proj_w  = (const float*)d_in[3];
    const float* proj_b  = (const float*)d_in[4];
    const float* gcn_w1  = (const float*)d_in[5];
    const float* gcn_b1  = (const float*)d_in[6];
    const float* gcn_w2  = (const float*)d_in[7];
    const float* gcn_b2  = (const float*)d_in[8];
    const float* gru_w_ih = (const float*)d_in[9];
    const float* gru_w_hh = (const float*)d_in[10];
    const float* gru_b_ih = (const float*)d_in[11];
    const float* gru_b_hh = (const float*)d_in[12];
    const float* attn_w  = (const float*)d_in[13];
    const float* attn_b  = (const float*)d_in[14];
    const float* pred_w1 = (const float*)d_in[15];
    const float* pred_b1 = (const float*)d_in[16];
    const float* pred_w2 = (const float*)d_in[17];
    const float* pred_b2 = (const float*)d_in[18];
    float* out = (float*)d_out;

    dim3 gAll(1, (MALL + 127) / 128);
    dim3 gG2(1, (TT * BB + 127) / 128);
    dim3 gGi(3, (TT * BB + 127) / 128);
    dim3 gGru(3, (BB + 127) / 128);
    const int agg1Blocks = (MALL * 32 + 255) / 256;
    const int agg2Blocks = (TT * BB * 32 + 255) / 256;
    dim3 gGather(BB, TT);

    // index 3 = batched proj GEMM (ncu captures launch 3)
    k_detect<<<1, 1024>>>((const unsigned int*)ei, BB);                          // 0
    k_cvt_ti<<<(BB + 255) / 256, 256>>>(ti);                                     // 1
    k_cvt_edges<<<(NE + 255) / 256, 256>>>(ei);                                  // 2
    sgemm2<0, 0, 1, 0, true, true><<<gAll, 256>>>(x, proj_w, proj_b, MALL, PP, FF); // 3
    k_transpose_wih<<<(384 * 256 + 255) / 256, 256>>>(gru_w_ih);                 // 4
    k_transpose_whh<<<(384 * 128 + 255) / 256, 256>>>(gru_w_hh);                 // 5

    // graph preprocessing
    k_init_deg<<<(NNODE + 255) / 256, 256>>>();
    k_deg_edges<<<(NE + 255) / 256, 256>>>();
    k_dinv<<<(NNODE + 255) / 256, 256>>>();
    k_scan<<<1, 1024>>>();
    k_selfloop<<<(NNODE + 255) / 256, 256>>>();
    k_fill_edges<<<(NE + 255) / 256, 256>>>();
    k_clear_masks<<<(NNODE + 255) / 256, 256>>>();
    k_mark_t<<<(BB + 255) / 256, 256>>>();
    k_mark_s<<<(NE + 255) / 256, 256>>>();
    k_mark_s2<<<(NNODE + 255) / 256, 256>>>();
    k_compact<<<(NNODE + 255) / 256, 256>>>();
    k_zero_h0<<<(BB * HH + 255) / 256, 256>>>();

    // GCN via linearity: agg first, GEMM on compact rows
    k_agg1_all<<<agg1Blocks, 256>>>();
    sgemm2<1, 0, 2, 1, true, true><<<gAll, 256>>>(nullptr, gcn_w1, gcn_b1, 0, GG, PP);
    k_agg2_all<<<agg2Blocks, 256>>>();
    sgemm2<2, 0, 3, 2, true, true><<<gG2, 256>>>(nullptr, gcn_w2, gcn_b2, 0, GG, GG);
    k_gather_all<<<gGather, 256>>>();

    // GI = tgt (8192 x 256) @ wihT + b_ih
    sgemm2<3, 1, 4, 0, false, true><<<gGi, 256>>>(nullptr, nullptr, gru_b_ih, TT * BB, 3 * HH, 2 * GG);

    for (int t = 0; t < TT; t++) {
        sgemm2<4, 2, 5, 0, false, true><<<gGru, 256>>>(nullptr, nullptr, gru_b_hh, BB, 3 * HH, HH);
        k_gru_pt<<<(BB * HH + 255) / 256, 256>>>(t);
    }

    k_final<<<BB, HH>>>(attn_w, attn_b, pred_w1, pred_b1, pred_w2, pred_b2, out);
}

// round 15
// speedup vs baseline: 1.6137x; 1.1145x over previous
#include <cuda_runtime.h>
#include <cuda_bf16.h>
#include <math.h>
#include <stdint.h>

#define TT 8
#define NNODE 40000
#define FF 256
#define PP 128
#define GG 128
#define HH 128
#define BB 1024
#define NE 640000
#define NNZ (NE + NNODE)
#define MALL (TT * NNODE)      // 320000 batched rows

// ------------------------- device scratch -------------------------
__device__ __align__(16) float g_h  [(size_t)MALL * PP];
__device__ __align__(16) float g_m  [(size_t)MALL * GG];
__device__ __align__(16) float g_hc [(size_t)MALL * GG];
__device__ __align__(16) float g_mc [(size_t)TT * BB * GG];
__device__ __align__(16) float g_h2 [(size_t)TT * BB * GG];
__device__ __align__(16) float g_tgt[(size_t)TT * BB * (2 * GG)];
__device__ __align__(16) float g_gi [(size_t)TT * BB * (3 * HH)];
__device__ __align__(16) float g_wihT[(size_t)(2 * GG) * (3 * HH)];
__device__ __align__(16) float g_outs[(size_t)TT * BB * HH];
__device__ __align__(16) float g_val [NNZ];
__device__ __align__(16) float g_dinv[NNODE];
__device__ __align__(16) int   g_col [NNZ];
__device__ __align__(16) int   g_rowptr[NNODE + 1];
__device__ __align__(16) int   g_deg [NNODE];
__device__ __align__(16) int   g_fill[NNODE];
__device__ __align__(16) int   g_src [NE];
__device__ __align__(16) int   g_dst [NE];
__device__ __align__(16) int   g_ti  [BB];
__device__ __align__(16) int   g_tmask[NNODE];
__device__ __align__(16) int   g_smask[NNODE];
__device__ __align__(16) int   g_snodes[NNODE];
__device__ __align__(16) int   g_sidx [NNODE];
__device__ __align__(16) int   g_tidx [NNODE];
__device__ __align__(16) int   g_tnodes[BB];
__device__ int g_nt;
__device__ int g_ns;
__device__ int g_is64;

// ------------------------- packed f32x2 FMA -------------------------
__device__ __forceinline__ void ffma2(unsigned long long& d, unsigned long long a,
                                      unsigned long long b) {
    asm("fma.rn.f32x2 %0, %1, %2, %0;" : "+l"(d) : "l"(a), "l"(b));
}
__device__ __forceinline__ unsigned long long bcast2(float v) {
    unsigned long long o;
    uint32_t u = __float_as_uint(v);
    asm("mov.b64 %0, {%1, %1};" : "=l"(o) : "r"(u));
    return o;
}
__device__ __forceinline__ void unpk2(float& lo, float& hi, unsigned long long p) {
    uint32_t a, b;
    asm("mov.b64 {%0, %1}, %2;" : "=r"(a), "=r"(b) : "l"(p));
    lo = __uint_as_float(a);
    hi = __uint_as_float(b);
}

// ------------------------- SGEMM (128x128x16, 8x8/thread, FFMA2, conflict-free) ------
// (byte-identical to R14 winner)
// AS: 0 ext, 1 g_m, 2 g_mc, 3 g_tgt ; BS: 0 ext, 1 g_wihT
// CS: 1 g_h, 2 g_hc, 3 g_h2, 4 g_gi ; MSEL: 0 param, 1 8*g_ns, 2 8*g_nt
template<int AS, int BS, int CS, int MSEL, bool RELU, bool BIAS>
__global__ void __launch_bounds__(256) sgemm2(const float* __restrict__ Aext,
                                              const float* __restrict__ Bext,
                                              const float* __restrict__ bias,
                                              int Mparam, int N, int K)
{
    int M;
    if constexpr (MSEL == 1)      M = 8 * g_ns;
    else if constexpr (MSEL == 2) M = 8 * g_nt;
    else                          M = Mparam;
    int rowBase = blockIdx.y * 128;
    if (rowBase >= M) return;

    const float* A;
    if constexpr (AS == 1)      A = g_m;
    else if constexpr (AS == 2) A = g_mc;
    else if constexpr (AS == 3) A = g_tgt;
    else                        A = Aext;
    const float* B;
    if constexpr (BS == 1)      B = g_wihT;
    else                        B = Bext;
    float* C;
    if constexpr (CS == 1)      C = g_h;
    else if constexpr (CS == 2) C = g_hc;
    else if constexpr (CS == 3) C = g_h2;
    else                        C = g_gi;

    const int BK = 16;
    __shared__ __align__(16) float As[2][BK][128];
    __shared__ __align__(16) float Bs[2][BK][128];
    int tid = threadIdx.x;
    int tx = tid % 16, ty = tid / 16;
    int colBase = blockIdx.x * 128;

    unsigned long long acc2[8][4];
#pragma unroll
    for (int i = 0; i < 8; i++)
#pragma unroll
        for (int j = 0; j < 4; j++) acc2[i][j] = 0ULL;

    int aRow = tid & 127;
    int aK   = (tid >> 7) * 8;
    int bRow = tid >> 4;
    int bC   = (tid & 15) * 4;

    int gr = rowBase + aRow;
    bool rowOK = (gr < M);
    const float* Arow = A + (size_t)(rowOK ? gr : 0) * K + aK;

    float4 va0, va1, vb0, vb1;

    va0 = make_float4(0.f, 0.f, 0.f, 0.f);
    va1 = make_float4(0.f, 0.f, 0.f, 0.f);
    if (rowOK) {
        va0 = *(const float4*)(Arow);
        va1 = *(const float4*)(Arow + 4);
    }
    vb0 = *(const float4*)(B + (size_t)bRow * N + colBase + bC);
    vb1 = *(const float4*)(B + (size_t)bRow * N + colBase + 64 + bC);
    As[0][aK + 0][aRow] = va0.x; As[0][aK + 1][aRow] = va0.y;
    As[0][aK + 2][aRow] = va0.z; As[0][aK + 3][aRow] = va0.w;
    As[0][aK + 4][aRow] = va1.x; As[0][aK + 5][aRow] = va1.y;
    As[0][aK + 6][aRow] = va1.z; As[0][aK + 7][aRow] = va1.w;
    *(float4*)&Bs[0][bRow][bC] = vb0;
    *(float4*)&Bs[0][bRow][64 + bC] = vb1;
    __syncthreads();

    int buf = 0;
    for (int k0 = 0; k0 < K; k0 += BK) {
        bool hasNext = (k0 + BK < K);
        if (hasNext) {
            int kn = k0 + BK;
            va0 = make_float4(0.f, 0.f, 0.f, 0.f);
            va1 = make_float4(0.f, 0.f, 0.f, 0.f);
            if (rowOK) {
                va0 = *(const float4*)(Arow + kn);
                va1 = *(const float4*)(Arow + kn + 4);
            }
            vb0 = *(const float4*)(B + (size_t)(kn + bRow) * N + colBase + bC);
            vb1 = *(const float4*)(B + (size_t)(kn + bRow) * N + colBase + 64 + bC);
        }
#pragma unroll
        for (int kk = 0; kk < BK; kk++) {
            float4 a0 = *(const float4*)&As[buf][kk][ty * 8];
            float4 a1 = *(const float4*)&As[buf][kk][ty * 8 + 4];
            unsigned long long av[8];
            av[0] = bcast2(a0.x); av[1] = bcast2(a0.y);
            av[2] = bcast2(a0.z); av[3] = bcast2(a0.w);
            av[4] = bcast2(a1.x); av[5] = bcast2(a1.y);
            av[6] = bcast2(a1.z); av[7] = bcast2(a1.w);
            ulonglong2 b0 = *(const ulonglong2*)&Bs[buf][kk][tx * 4];
            ulonglong2 b1 = *(const ulonglong2*)&Bs[buf][kk][64 + tx * 4];
            unsigned long long bv[4] = {b0.x, b0.y, b1.x, b1.y};
#pragma unroll
            for (int i = 0; i < 8; i++)
#pragma unroll
                for (int j = 0; j < 4; j++) ffma2(acc2[i][j], av[i], bv[j]);
        }
        if (hasNext) {
            int nb = buf ^ 1;
            As[nb][aK + 0][aRow] = va0.x; As[nb][aK + 1][aRow] = va0.y;
            As[nb][aK + 2][aRow] = va0.z; As[nb][aK + 3][aRow] = va0.w;
            As[nb][aK + 4][aRow] = va1.x; As[nb][aK + 5][aRow] = va1.y;
            As[nb][aK + 6][aRow] = va1.z; As[nb][aK + 7][aRow] = va1.w;
            *(float4*)&Bs[nb][bRow][bC] = vb0;
            *(float4*)&Bs[nb][bRow][64 + bC] = vb1;
            __syncthreads();
        }
        buf ^= 1;
    }

#pragma unroll
    for (int i = 0; i < 8; i++) {
        int grr = rowBase + ty * 8 + i;
        if (grr >= M) continue;
        float c[8];
#pragma unroll
        for (int j = 0; j < 4; j++) unpk2(c[2 * j], c[2 * j + 1], acc2[i][j]);
        int gc0 = colBase + tx * 4;
        int gc1 = colBase + 64 + tx * 4;
        float4 o0, o1;
        o0.x = c[0]; o0.y = c[1]; o0.z = c[2]; o0.w = c[3];
        o1.x = c[4]; o1.y = c[5]; o1.z = c[6]; o1.w = c[7];
        if (BIAS) {
            o0.x += bias[gc0]; o0.y += bias[gc0 + 1];
            o0.z += bias[gc0 + 2]; o0.w += bias[gc0 + 3];
            o1.x += bias[gc1]; o1.y += bias[gc1 + 1];
            o1.z += bias[gc1 + 2]; o1.w += bias[gc1 + 3];
        }
        if (RELU) {
            o0.x = fmaxf(o0.x, 0.f); o0.y = fmaxf(o0.y, 0.f);
            o0.z = fmaxf(o0.z, 0.f); o0.w = fmaxf(o0.w, 0.f);
            o1.x = fmaxf(o1.x, 0.f); o1.y = fmaxf(o1.y, 0.f);
            o1.z = fmaxf(o1.z, 0.f); o1.w = fmaxf(o1.w, 0.f);
        }
        *(float4*)(C + (size_t)grr * N + gc0) = o0;
        *(float4*)(C + (size_t)grr * N + gc1) = o1;
    }
}

// ------------------------- index dtype detection + conversion -------------------------
__global__ void k_detect(const unsigned int* __restrict__ wdata, int n_elems) {
    __shared__ int bad;
    if (threadIdx.x == 0) bad = 0;
    __syncthreads();
    int limit = n_elems < 4096 ? n_elems : 4096;
    for (int i = threadIdx.x; i < limit; i += blockDim.x)
        if (wdata[2 * i + 1] != 0u) bad = 1;
    __syncthreads();
    if (threadIdx.x == 0) g_is64 = bad ? 0 : 1;
}

__device__ __forceinline__ int clampN(int v) {
    return v < 0 ? 0 : (v >= NNODE ? NNODE - 1 : v);
}

__global__ void k_cvt_edges(const void* __restrict__ ei) {
    int e = blockIdx.x * blockDim.x + threadIdx.x;
    if (e < NE) {
        int s, d;
        if (g_is64) {
            const long long* p = (const long long*)ei;
            s = (int)p[e]; d = (int)p[NE + e];
        } else {
            const int* p = (const int*)ei;
            s = p[e]; d = p[NE + e];
        }
        g_src[e] = clampN(s);
        g_dst[e] = clampN(d);
    }
}

__global__ void k_cvt_ti(const void* __restrict__ ti) {
    int b = blockIdx.x * blockDim.x + threadIdx.x;
    if (b < BB) {
        int v;
        if (g_is64) v = (int)((const long long*)ti)[b];
        else        v = ((const int*)ti)[b];
        g_ti[b] = clampN(v);
    }
}

// ------------------------- graph preprocessing -------------------------
__global__ void k_init_deg() {
    int i = blockIdx.x * blockDim.x + threadIdx.x;
    if (i < NNODE) { g_deg[i] = 1; g_fill[i] = 0; g_tmask[i] = 0; g_smask[i] = 0; }
    if (i == 0) { g_nt = 0; g_ns = 0; }
}

__global__ void k_deg_edges() {
    int e = blockIdx.x * blockDim.x + threadIdx.x;
    if (e < NE) atomicAdd(&g_deg[g_dst[e]], 1);
}

__global__ void k_dinv() {
    int i = blockIdx.x * blockDim.x + threadIdx.x;
    if (i < NNODE) g_dinv[i] = rsqrtf((float)g_deg[i]);
}

__global__ void k_scan() {
    const int CH = 40;
    int t = threadIdx.x;
    int lane = t & 31, wid = t >> 5;
    int beg = t * CH;
    int sum = 0;
    for (int i = 0; i < CH; i++) {
        int idx = beg + i;
        if (idx < NNODE) sum += g_deg[idx];
    }
    int v = sum;
    for (int o = 1; o < 32; o <<= 1) {
        int u = __shfl_up_sync(0xffffffffu, v, o);
        if (lane >= o) v += u;
    }
    __shared__ int wsum[32];
    if (lane == 31) wsum[wid] = v;
    __syncthreads();
    if (wid == 0) {
        int w2 = wsum[lane];
        for (int o = 1; o < 32; o <<= 1) {
            int u = __shfl_up_sync(0xffffffffu, w2, o);
            if (lane >= o) w2 += u;
        }
        wsum[lane] = w2;
    }
    __syncthreads();
    int run = v - sum + (wid > 0 ? wsum[wid - 1] : 0);
    for (int i = 0; i < CH; i++) {
        int idx = beg + i;
        if (idx < NNODE) {
            g_rowptr[idx] = run;
            run += g_deg[idx];
        }
    }
    if (t == 1023) g_rowptr[NNODE] = run;
}

__global__ void k_selfloop() {
    int n = blockIdx.x * blockDim.x + threadIdx.x;
    if (n < NNODE) {
        int pos = g_rowptr[n];
        g_col[pos] = n;
        float d = g_dinv[n];
        g_val[pos] = d * d;
        g_fill[n] = 1;
    }
}

__global__ void k_fill_edges() {
    int e = blockIdx.x * blockDim.x + threadIdx.x;
    if (e < NE) {
        int s = g_src[e];
        int d = g_dst[e];
        int pos = g_rowptr[d] + atomicAdd(&g_fill[d], 1);
        g_col[pos] = s;
        g_val[pos] = g_dinv[s] * g_dinv[d];
    }
}

// ------------------------- target-neighborhood compaction -------------------------
__global__ void k_mark_t() {
    int b = blockIdx.x * blockDim.x + threadIdx.x;
    if (b < BB) { g_tmask[g_ti[b]] = 1; g_smask[g_ti[b]] = 1; }
}
__global__ void k_mark_s() {
    int e = blockIdx.x * blockDim.x + threadIdx.x;
    if (e < NE && g_tmask[g_dst[e]]) g_smask[g_src[e]] = 1;
}
__global__ void k_compact() {
    int n = blockIdx.x * blockDim.x + threadIdx.x;
    if (n < NNODE) {
        if (g_tmask[n]) {
            int ix = atomicAdd(&g_nt, 1);
            g_tnodes[ix] = n;
            g_tidx[n] = ix;
        }
        if (g_smask[n]) {
            int ix = atomicAdd(&g_ns, 1);
            g_snodes[ix] = n;
            g_sidx[n] = ix;
        }
    }
}

// ------------------------- batched aggregations (pre-GEMM, linearity) ----------------
__global__ void k_agg1_all()
{
    int warp = (blockIdx.x * blockDim.x + threadIdx.x) >> 5;
    int lane = threadIdx.x & 31;
    int ns = g_ns;
    if (warp >= TT * ns) return;
    int t = warp / ns;
    int i = warp - t * ns;
    int node = g_snodes[i];
    int s0 = g_rowptr[node], s1 = g_rowptr[node + 1];
    const float4* h4 = (const float4*)g_h;
    size_t hbase = (size_t)t * NNODE * 32;
    float4 acc = make_float4(0.f, 0.f, 0.f, 0.f);
    for (int e = s0; e < s1; e++) {
        float v = g_val[e];
        float4 x = h4[hbase + (size_t)g_col[e] * 32 + lane];
        acc.x = fmaf(v, x.x, acc.x); acc.y = fmaf(v, x.y, acc.y);
        acc.z = fmaf(v, x.z, acc.z); acc.w = fmaf(v, x.w, acc.w);
    }
    ((float4*)g_m)[(size_t)warp * 32 + lane] = acc;
}

__global__ void k_agg2_all()
{
    int warp = (blockIdx.x * blockDim.x + threadIdx.x) >> 5;
    int lane = threadIdx.x & 31;
    int nt = g_nt;
    if (warp >= TT * nt) return;
    int t = warp / nt;
    int i = warp - t * nt;
    int node = g_tnodes[i];
    int s0 = g_rowptr[node], s1 = g_rowptr[node + 1];
    const float4* h4 = (const float4*)g_hc;
    size_t hbase = (size_t)t * g_ns * 32;
    float4 acc = make_float4(0.f, 0.f, 0.f, 0.f);
    for (int e = s0; e < s1; e++) {
        float v = g_val[e];
        float4 x = h4[hbase + (size_t)g_sidx[g_col[e]] * 32 + lane];
        acc.x = fmaf(v, x.x, acc.x); acc.y = fmaf(v, x.y, acc.y);
        acc.z = fmaf(v, x.z, acc.z); acc.w = fmaf(v, x.w, acc.w);
    }
    ((float4*)g_mc)[(size_t)warp * 32 + lane] = acc;
}

// ------------------------- gather targets (all t) -------------------------
__global__ void k_gather_all() {
    int b = blockIdx.x;
    int t = blockIdx.y;
    int f = threadIdx.x;                   // 256
    int node = g_ti[b];
    float v = (f < GG) ? g_hc[((size_t)t * g_ns + g_sidx[node]) * GG + f]
                       : g_h2[((size_t)t * g_nt + g_tidx[node]) * GG + (f - GG)];
    g_tgt[((size_t)t * BB + b) * (2 * GG) + f] = v;
}

// ------------------------- weight transpose for GI GEMM -------------------------
__global__ void k_transpose_wih(const float* __restrict__ w) {
    int i = blockIdx.x * blockDim.x + threadIdx.x;
    if (i < 384 * 256) {
        int jj = i / 256, k = i % 256;
        g_wihT[(size_t)k * 384 + jj] = w[i];
    }
}

// ------------------------- fused persistent GRU -------------------------
// grid = BB/8 = 128 CTAs x 384 threads. CTA owns 8 batch rows, loops all t.
// Gh[r][j] = dot(h[r,:], whh[j,:]) (whh row-major (384,128), contiguous per thread,
// L1-resident after t=0). Pointwise fused via smem gate buffer.
__device__ __forceinline__ float sigmoidf_(float x) { return 1.f / (1.f + expf(-x)); }

__global__ void __launch_bounds__(384) k_gru_fused(const float* __restrict__ whh,
                                                   const float* __restrict__ b_hh)
{
    __shared__ float sh_h[8][128];
    __shared__ float sh_g[8][384];
    int j = threadIdx.x;                  // 0..383
    int rowBase = blockIdx.x * 8;

    for (int idx = j; idx < 8 * 128; idx += 384) ((float*)sh_h)[idx] = 0.f;
    __syncthreads();

    const float* wrow = whh + (size_t)j * 128;
    float bj = b_hh[j];

    for (int t = 0; t < TT; t++) {
        float acc[8];
#pragma unroll
        for (int r = 0; r < 8; r++) acc[r] = bj;
#pragma unroll 4
        for (int k = 0; k < 128; k += 4) {
            float4 w4 = *(const float4*)(wrow + k);
#pragma unroll
            for (int r = 0; r < 8; r++) {
                float4 h4 = *(const float4*)&sh_h[r][k];
                acc[r] = fmaf(h4.x, w4.x, acc[r]);
                acc[r] = fmaf(h4.y, w4.y, acc[r]);
                acc[r] = fmaf(h4.z, w4.z, acc[r]);
                acc[r] = fmaf(h4.w, w4.w, acc[r]);
            }
        }
#pragma unroll
        for (int r = 0; r < 8; r++) sh_g[r][j] = acc[r];
        __syncthreads();
        // pointwise: 8*128 = 1024 elems over 384 threads
        for (int idx = j; idx < 8 * 128; idx += 384) {
            int r = idx >> 7, c = idx & 127;
            int b = rowBase + r;
            size_t gir = ((size_t)t * BB + b) * 384;
            float hr = sh_g[r][c], hz = sh_g[r][128 + c], hg = sh_g[r][256 + c];
            float rr = sigmoidf_(g_gi[gir + c] + hr);
            float zz = sigmoidf_(g_gi[gir + 128 + c] + hz);
            float gg = tanhf(g_gi[gir + 256 + c] + rr * hg);
            float hn = (1.f - zz) * gg + zz * sh_h[r][c];
            sh_h[r][c] = hn;
            g_outs[((size_t)t * BB + b) * HH + c] = hn;
        }
        __syncthreads();
    }
}

// ------------------------- attention + prediction head -------------------------
__global__ void k_final(const float* __restrict__ attn_w, const float* __restrict__ attn_b,
                        const float* __restrict__ pw1, const float* __restrict__ pb1,
                        const float* __restrict__ pw2, const float* __restrict__ pb2,
                        float* __restrict__ out)
{
    int b = blockIdx.x;
    int j = threadIdx.x;                   // 128
    __shared__ float so[TT][HH];
    __shared__ float red[HH];
    __shared__ float sc[TT];
    __shared__ float w8[TT];
    __shared__ float hm[16];

#pragma unroll
    for (int t = 0; t < TT; t++) so[t][j] = g_outs[((size_t)t * BB + b) * HH + j];
    float aw = attn_w[j];
    __syncthreads();

    for (int t = 0; t < TT; t++) {
        red[j] = so[t][j] * aw;
        __syncthreads();
        for (int off = 64; off > 0; off >>= 1) {
            if (j < off) red[j] += red[j + off];
            __syncthreads();
        }
        if (j == 0) sc[t] = tanhf(red[0] + attn_b[0]);
        __syncthreads();
    }
    if (j == 0) {
        float mx = sc[0];
        for (int t = 1; t < TT; t++) mx = fmaxf(mx, sc[t]);
        float s = 0.f;
        for (int t = 0; t < TT; t++) { w8[t] = expf(sc[t] - mx); s += w8[t]; }
        float inv = 1.f / s;
        for (int t = 0; t < TT; t++) w8[t] *= inv;
    }
    __syncthreads();
    float rep = 0.f;
#pragma unroll
    for (int t = 0; t < TT; t++) rep = fmaf(w8[t], so[t][j], rep);
    red[j] = rep;
    __syncthreads();
    if (j < 16) {
        float s = pb1[j];
        for (int k = 0; k < HH; k++) s = fmaf(red[k], pw1[k * 16 + j], s);
        hm[j] = fmaxf(s, 0.f);
    }
    __syncthreads();
    if (j == 0) {
        float p = pb2[0];
#pragma unroll
        for (int k = 0; k < 16; k++) p = fmaf(hm[k], pw2[k], p);
        out[b] = p;
    }
    if (j < TT) out[BB + b * TT + j] = w8[j];
}

// ------------------------- launch -------------------------
extern "C" void kernel_launch(void* const* d_in, const int* in_sizes, int n_in,
                              void* d_out, int out_size)
{
    const float* x       = (const float*)d_in[0];
    const void*  ei      = d_in[1];
    const void*  ti      = d_in[2];
    const float* proj_w  = (const float*)d_in[3];
    const float* proj_b  = (const float*)d_in[4];
    const float* gcn_w1  = (const float*)d_in[5];
    const float* gcn_b1  = (const float*)d_in[6];
    const float* gcn_w2  = (const float*)d_in[7];
    const float* gcn_b2  = (const float*)d_in[8];
    const float* gru_w_ih = (const float*)d_in[9];
    const float* gru_w_hh = (const float*)d_in[10];
    const float* gru_b_ih = (const float*)d_in[11];
    const float* gru_b_hh = (const float*)d_in[12];
    const float* attn_w  = (const float*)d_in[13];
    const float* attn_b  = (const float*)d_in[14];
    const float* pred_w1 = (const float*)d_in[15];
    const float* pred_b1 = (const float*)d_in[16];
    const float* pred_w2 = (const float*)d_in[17];
    const float* pred_b2 = (const float*)d_in[18];
    float* out = (float*)d_out;

    dim3 gAll(1, (MALL + 127) / 128);
    dim3 gG2(1, (TT * BB + 127) / 128);
    dim3 gGi(3, (TT * BB + 127) / 128);
    const int agg1Blocks = (MALL * 32 + 255) / 256;
    const int agg2Blocks = (TT * BB * 32 + 255) / 256;
    dim3 gGather(BB, TT);

    // index 3 = batched proj GEMM (ncu captures launch 3)
    k_detect<<<1, 1024>>>((const unsigned int*)ei, BB);                          // 0
    k_cvt_ti<<<(BB + 255) / 256, 256>>>(ti);                                     // 1
    k_cvt_edges<<<(NE + 255) / 256, 256>>>(ei);                                  // 2
    sgemm2<0, 0, 1, 0, true, true><<<gAll, 256>>>(x, proj_w, proj_b, MALL, PP, FF); // 3
    k_transpose_wih<<<(384 * 256 + 255) / 256, 256>>>(gru_w_ih);                 // 4

    // graph preprocessing
    k_init_deg<<<(NNODE + 255) / 256, 256>>>();
    k_deg_edges<<<(NE + 255) / 256, 256>>>();
    k_dinv<<<(NNODE + 255) / 256, 256>>>();
    k_scan<<<1, 1024>>>();
    k_selfloop<<<(NNODE + 255) / 256, 256>>>();
    k_fill_edges<<<(NE + 255) / 256, 256>>>();
    k_mark_t<<<(BB + 255) / 256, 256>>>();
    k_mark_s<<<(NE + 255) / 256, 256>>>();
    k_compact<<<(NNODE + 255) / 256, 256>>>();

    // GCN via linearity: agg first, GEMM on compact rows
    k_agg1_all<<<agg1Blocks, 256>>>();
    sgemm2<1, 0, 2, 1, true, true><<<gAll, 256>>>(nullptr, gcn_w1, gcn_b1, 0, GG, PP);
    k_agg2_all<<<agg2Blocks, 256>>>();
    sgemm2<2, 0, 3, 2, true, true><<<gG2, 256>>>(nullptr, gcn_w2, gcn_b2, 0, GG, GG);
    k_gather_all<<<gGather, 256>>>();

    // GI = tgt (8192 x 256) @ wihT + b_ih
    sgemm2<3, 1, 4, 0, false, true><<<gGi, 256>>>(nullptr, nullptr, gru_b_ih, TT * BB, 3 * HH, 2 * GG);

    // fused GRU: all 8 steps in one persistent kernel
    k_gru_fused<<<BB / 8, 384>>>(gru_w_hh, gru_b_hh);

    k_final<<<BB, HH>>>(attn_w, attn_b, pred_w1, pred_b1, pred_w2, pred_b2, out);
}